// round 2
// baseline (speedup 1.0000x reference)
#include <cuda_runtime.h>
#include <cstdint>
#include <math.h>

#define BB 16
#define NN 1024
#define CC 256

// ---------------- scratch (__device__ globals: allocation-free) ----------------
__device__ float          g_Wp[CC];            // W @ pooling  (row dots)
__device__ float          g_scal[2];           // [0] = 1/||p||, [1] = b.p
__device__ float          g_t[BB * NN];        // x . Wp  per node
__device__ float          g_y[BB * NN];        // scores
__device__ float          g_mf[BB * NN];       // new mask (float)
__device__ int            g_cnt[BB * NN];      // nnz per adj row
__device__ unsigned short g_idx[(size_t)BB * NN * NN]; // nnz col indices per row (32 MB)
__device__ int            g_rows[BB * NN];     // compacted surviving row ids per batch
__device__ int            g_nrows[BB];         // surviving count per batch
__device__ float          g_gc[(size_t)BB * NN * CC];  // gathered sums, compact (16 MB)

// ---------------- f32x2 helpers (sm_103a packed fp32 FMA) ----------------
__device__ __forceinline__ unsigned long long pack2(float lo, float hi) {
    unsigned long long r;
    asm("mov.b64 %0, {%1, %2};" : "=l"(r) : "f"(lo), "f"(hi));
    return r;
}
__device__ __forceinline__ void fma2(unsigned long long& d,
                                     unsigned long long a,
                                     unsigned long long b) {
    asm("fma.rn.f32x2 %0, %1, %2, %0;" : "+l"(d) : "l"(a), "l"(b));
}
__device__ __forceinline__ void unpack2(unsigned long long v, float& lo, float& hi) {
    asm("mov.b64 {%0, %1}, %2;" : "=f"(lo), "=f"(hi) : "l"(v));
}

// ---------------- K_zero: zero the whole output buffer ----------------
__global__ void k_zero(float* __restrict__ out, long long n_elem) {
    long long n4 = n_elem >> 2;
    float4 z = make_float4(0.f, 0.f, 0.f, 0.f);
    float4* o = reinterpret_cast<float4*>(out);
    long long stride = (long long)gridDim.x * blockDim.x;
    for (long long i = (long long)blockIdx.x * blockDim.x + threadIdx.x; i < n4; i += stride)
        o[i] = z;
    if (blockIdx.x == 0 && threadIdx.x == 0)
        for (long long r = n4 << 2; r < n_elem; r++) out[r] = 0.f;
}

// ---------------- K_prep: Wp[k] = sum_c W[k][c] p[c] ; 1/||p|| ; b.p ----------------
__global__ void k_prep(const float* __restrict__ W,
                       const float* __restrict__ b,
                       const float* __restrict__ p) {
    __shared__ float ps[CC];
    __shared__ float s1[CC], s2[CC];
    int c = threadIdx.x;
    ps[c] = p[c];
    __syncthreads();
    // FIX: W @ p = row dot (was computing W^T p)
    float acc = 0.f;
    const float* wr = W + (size_t)c * CC;
    for (int k = 0; k < CC; k++) acc += wr[k] * ps[k];
    g_Wp[c] = acc;
    float pc = ps[c];
    s1[c] = pc * pc;
    s2[c] = b[c] * pc;
    __syncthreads();
    for (int off = CC / 2; off > 0; off >>= 1) {
        if (c < off) { s1[c] += s1[c + off]; s2[c] += s2[c + off]; }
        __syncthreads();
    }
    if (c == 0) {
        g_scal[0] = 1.0f / sqrtf(s1[0]);
        g_scal[1] = s2[0];
    }
}

// ---------------- K_t: t[b,n] = x[b,n,:] . Wp  (warp per row) ----------------
__global__ void k_t(const float* __restrict__ x) {
    __shared__ float wp[CC];
    int tid = threadIdx.x;
    wp[tid] = g_Wp[tid];
    __syncthreads();
    int warp = tid >> 5, lane = tid & 31;
    int row = blockIdx.x * 8 + warp;           // [0, BB*NN)
    const float* xr = x + (size_t)row * CC;
    float acc = 0.f;
#pragma unroll 4
    for (int j = lane; j < CC; j += 32) acc += xr[j] * wp[j];
    for (int o = 16; o > 0; o >>= 1) acc += __shfl_down_sync(0xffffffffu, acc, o);
    if (lane == 0) g_t[row] = acc;
}

// ---------------- K_adjscan: one pass over adj -> y scores + nnz lists ----------------
__global__ void k_adjscan(const float* __restrict__ adj) {
    __shared__ float s[NN];
    int tid = threadIdx.x;
    int b = blockIdx.x >> 7;           // 128 blocks per batch
    int chunk = blockIdx.x & 127;
    for (int i = tid; i < NN; i += blockDim.x) s[i] = g_t[b * NN + i];
    __syncthreads();
    int warp = tid >> 5, lane = tid & 31;
    int n = chunk * 8 + warp;
    const float* ar = adj + ((size_t)b * NN + n) * NN;
    unsigned short* ir = g_idx + ((size_t)b * NN + n) * NN;
    float acc = 0.f;
    int cnt = 0;
    for (int m0 = 0; m0 < NN; m0 += 32) {
        float v = ar[m0 + lane];
        acc += v * s[m0 + lane];
        unsigned ball = __ballot_sync(0xffffffffu, v != 0.0f);
        if (v != 0.0f) {
            int pos = cnt + __popc(ball & ((1u << lane) - 1u));
            ir[pos] = (unsigned short)(m0 + lane);
        }
        cnt += __popc(ball);
    }
    for (int o = 16; o > 0; o >>= 1) acc += __shfl_down_sync(0xffffffffu, acc, o);
    if (lane == 0) {
        g_cnt[b * NN + n] = cnt;
        g_y[b * NN + n] = (acc + g_scal[1]) * g_scal[0];
    }
}

// ---------------- K_rank: pairwise stable ranking, mask, compaction ----------------
__global__ void k_rank(const int* __restrict__ mask,
                       const int* __restrict__ n_nodes,
                       float* __restrict__ out_mask,
                       float* __restrict__ out_nn) {
    int b = blockIdx.x;
    int i = threadIdx.x;
    __shared__ float ys[NN];
    __shared__ int   ms[NN];
    __shared__ int   sc[NN];
    float yi = g_y[b * NN + i];
    int   mi = mask[b * NN + i];
    ys[i] = yi;
    ms[i] = mi;
    __syncthreads();
    // rank among masked nodes strictly before i in (stable ascending) sort order
    int r = 0;
    for (int j = 0; j < NN; j++) {
        float yj = ys[j];
        if (yj < yi || (yj == yi && j < i)) r += ms[j];
    }
    int nrem = (int)((float)n_nodes[b] * 0.5f);  // (1 - POOL_RATIO) = 0.5 exact
    int nm = (mi != 0) ? ((r < nrem) ? 0 : 1) : 0;
    g_mf[b * NN + i] = (float)nm;
    out_mask[b * NN + i] = (float)nm;
    // inclusive Hillis-Steele scan for deterministic compaction
    sc[i] = nm;
    __syncthreads();
    for (int off = 1; off < NN; off <<= 1) {
        int v = (i >= off) ? sc[i - off] : 0;
        __syncthreads();
        sc[i] += v;
        __syncthreads();
    }
    int excl = sc[i] - nm;
    if (nm) g_rows[b * NN + excl] = i;
    if (i == 0) {
        g_nrows[b] = sc[NN - 1];
        out_nn[b] = (float)(n_nodes[b] - nrem);
    }
}

// ---------------- K_gather: g_gc[compact row] = sum of x rows over nnz ----------------
__global__ void k_gather(const float* __restrict__ x) {
    int b = blockIdx.y;
    int pos = blockIdx.x;
    if (pos >= g_nrows[b]) return;
    int row = g_rows[b * NN + pos];
    int cnt = g_cnt[b * NN + row];
    __shared__ unsigned short sidx[NN];
    const unsigned short* ir = g_idx + ((size_t)b * NN + row) * NN;
    for (int t = threadIdx.x; t < cnt; t += blockDim.x) sidx[t] = ir[t];
    __syncthreads();
    int c = threadIdx.x;
    const float* xb = x + (size_t)b * NN * CC;
    float a0 = 0.f, a1 = 0.f, a2 = 0.f, a3 = 0.f;
    int t = 0;
    for (; t + 4 <= cnt; t += 4) {
        a0 += xb[(int)sidx[t + 0] * CC + c];
        a1 += xb[(int)sidx[t + 1] * CC + c];
        a2 += xb[(int)sidx[t + 2] * CC + c];
        a3 += xb[(int)sidx[t + 3] * CC + c];
    }
    for (; t < cnt; t++) a0 += xb[(int)sidx[t] * CC + c];
    g_gc[((size_t)b * NN + pos) * CC + c] = (a0 + a1) + (a2 + a3);
}

// ---------------- K_gemm: x_out[masked rows] = (g_gc @ W + b) * tanh(y) ----------------
#define GM 128
#define GN 128
#define GK 16

__global__ __launch_bounds__(256) void k_gemm(const float* __restrict__ W,
                                              const float* __restrict__ bvec,
                                              float* __restrict__ out_x) {
    int b = blockIdx.z;
    int nrows = g_nrows[b];
    int row0 = blockIdx.x * GM;
    if (row0 >= nrows) return;
    int col0 = blockIdx.y * GN;
    int rows_in = nrows - row0;
    if (rows_in > GM) rows_in = GM;

    __shared__ float As[2][GK][GM + 4];
    __shared__ float Bs[2][GK][GN];

    const float* A = g_gc + ((size_t)b * NN + row0) * CC;
    int tid = threadIdx.x;
    int tx = tid & 15;   // row group: rows tx*8 .. tx*8+7
    int ty = tid >> 4;   // col group: cols ty*8 .. ty*8+7

    unsigned long long acc[8][4];
#pragma unroll
    for (int i = 0; i < 8; i++)
#pragma unroll
        for (int j = 0; j < 4; j++) acc[i][j] = 0ULL;  // bits == (0.f, 0.f)

    float4 ra[2], rb[2];

#define LOAD_A(kt)                                                              \
    {                                                                           \
        _Pragma("unroll") for (int u = 0; u < 2; u++) {                         \
            int idx = tid + u * 256;                                            \
            int m = idx >> 2, k4 = idx & 3;                                     \
            ra[u] = (m < rows_in)                                               \
                        ? *(const float4*)(A + (size_t)m * CC + (kt) + k4 * 4)  \
                        : make_float4(0.f, 0.f, 0.f, 0.f);                      \
        }                                                                       \
    }
#define LOAD_B(kt)                                                              \
    {                                                                           \
        _Pragma("unroll") for (int u = 0; u < 2; u++) {                         \
            int idx = tid + u * 256;                                            \
            int k = idx >> 5, c4 = idx & 31;                                    \
            rb[u] = *(const float4*)(W + (size_t)((kt) + k) * CC + col0 + c4 * 4); \
        }                                                                       \
    }
#define STORE_AB(buf)                                                           \
    {                                                                           \
        _Pragma("unroll") for (int u = 0; u < 2; u++) {                         \
            int idx = tid + u * 256;                                            \
            int m = idx >> 2, k4 = idx & 3;                                     \
            As[buf][k4 * 4 + 0][m] = ra[u].x;                                   \
            As[buf][k4 * 4 + 1][m] = ra[u].y;                                   \
            As[buf][k4 * 4 + 2][m] = ra[u].z;                                   \
            As[buf][k4 * 4 + 3][m] = ra[u].w;                                   \
            int k = idx >> 5, c4 = idx & 31;                                    \
            *(float4*)&Bs[buf][k][c4 * 4] = rb[u];                              \
        }                                                                       \
    }

    LOAD_A(0)
    LOAD_B(0)
    STORE_AB(0)
    __syncthreads();

    int buf = 0;
    for (int kt = 0; kt < CC; kt += GK) {
        if (kt + GK < CC) {
            LOAD_A(kt + GK)
            LOAD_B(kt + GK)
        }
#pragma unroll
        for (int k = 0; k < GK; k++) {
            float af[8], bf[8];
            *(float4*)&af[0] = *(const float4*)&As[buf][k][tx * 8];
            *(float4*)&af[4] = *(const float4*)&As[buf][k][tx * 8 + 4];
            *(float4*)&bf[0] = *(const float4*)&Bs[buf][k][ty * 8];
            *(float4*)&bf[4] = *(const float4*)&Bs[buf][k][ty * 8 + 4];
            unsigned long long b2[4];
#pragma unroll
            for (int j = 0; j < 4; j++) b2[j] = pack2(bf[2 * j], bf[2 * j + 1]);
#pragma unroll
            for (int i = 0; i < 8; i++) {
                unsigned long long a2 = pack2(af[i], af[i]);
#pragma unroll
                for (int j = 0; j < 4; j++) fma2(acc[i][j], a2, b2[j]);
            }
        }
        if (kt + GK < CC) {
            STORE_AB(buf ^ 1)
        }
        __syncthreads();
        buf ^= 1;
    }

    // epilogue: scatter rows to their original node positions with bias + tanh scale
#pragma unroll
    for (int i = 0; i < 8; i++) {
        int m = tx * 8 + i;
        if (row0 + m < nrows) {
            int n = g_rows[b * NN + row0 + m];
            float tval = tanhf(g_y[b * NN + n]);
            float res[8];
#pragma unroll
            for (int j = 0; j < 4; j++) unpack2(acc[i][j], res[2 * j], res[2 * j + 1]);
#pragma unroll
            for (int j = 0; j < 8; j++)
                res[j] = (res[j] + bvec[col0 + ty * 8 + j]) * tval;
            float* orow = out_x + ((size_t)b * NN + n) * CC + col0 + ty * 8;
            *(float4*)&orow[0] = *(float4*)&res[0];
            *(float4*)&orow[4] = *(float4*)&res[4];
        }
    }
#undef LOAD_A
#undef LOAD_B
#undef STORE_AB
}

// ---------------- K_adjout: scatter 1.0 at surviving nnz positions ----------------
__global__ void k_adjout(float* __restrict__ out_adj) {
    int b = blockIdx.y;
    int pos = blockIdx.x;
    if (pos >= g_nrows[b]) return;
    int n = g_rows[b * NN + pos];
    int cnt = g_cnt[b * NN + n];
    const unsigned short* ir = g_idx + ((size_t)b * NN + n) * NN;
    float* orow = out_adj + ((size_t)b * NN + n) * NN;
    for (int t = threadIdx.x; t < cnt; t += blockDim.x) {
        int m = ir[t];
        if (g_mf[b * NN + m] != 0.0f) orow[m] = 1.0f;
    }
}

// ---------------- launch ----------------
extern "C" void kernel_launch(void* const* d_in, const int* in_sizes, int n_in,
                              void* d_out, int out_size) {
    const float* x    = (const float*)d_in[0];  // [B,N,C]
    const float* adj  = (const float*)d_in[1];  // [B,N,N]
    const int*   mask = (const int*)d_in[2];    // [B,N]
    const int*   nnod = (const int*)d_in[3];    // [B]
    const float* W    = (const float*)d_in[4];  // [C,C]
    const float* bv   = (const float*)d_in[5];  // [C]
    const float* pool = (const float*)d_in[6];  // [C,1]

    float* out = (float*)d_out;
    float* out_x    = out;                                   // B*N*C
    float* out_adj  = out + (size_t)BB * NN * CC;            // B*N*N
    float* out_mask = out_adj + (size_t)BB * NN * NN;        // B*N
    float* out_nn   = out_mask + (size_t)BB * NN;            // B

    k_zero<<<4096, 256>>>(out, (long long)out_size);
    k_prep<<<1, CC>>>(W, bv, pool);
    k_t<<<(BB * NN) / 8, 256>>>(x);
    k_adjscan<<<(BB * NN) / 8, 256>>>(adj);
    k_rank<<<BB, NN>>>(mask, nnod, out_mask, out_nn);
    k_gather<<<dim3(NN, BB), CC>>>(x);
    k_gemm<<<dim3(NN / GM, CC / GN, BB), 256>>>(W, bv, out_x);
    k_adjout<<<dim3(NN, BB), 64>>>(out_adj);
}

// round 3
// speedup vs baseline: 1.1706x; 1.1706x over previous
#include <cuda_runtime.h>
#include <cstdint>
#include <math.h>

#define BB 16
#define NN 1024
#define CC 256

// ---------------- scratch (__device__ globals: allocation-free) ----------------
__device__ float          g_Wp[CC];            // W @ pooling  (row dots)
__device__ float          g_scal[2];           // [0] = 1/||p||, [1] = b.p
__device__ float          g_t[BB * NN];        // x . Wp  per node
__device__ float          g_y[BB * NN];        // scores
__device__ float          g_mf[BB * NN];       // new mask (float)
__device__ int            g_cnt[BB * NN];      // nnz per adj row
__device__ unsigned short g_idx[(size_t)BB * NN * NN]; // nnz col indices per row (32 MB)
__device__ int            g_rows[BB * NN];     // compacted surviving row ids per batch
__device__ int            g_nrows[BB];         // surviving count per batch
__device__ float          g_gc[(size_t)BB * NN * CC];  // gathered sums, compact (16 MB)

// ---------------- f32x2 helpers (sm_103a packed fp32 FMA) ----------------
__device__ __forceinline__ unsigned long long pack2(float lo, float hi) {
    unsigned long long r;
    asm("mov.b64 %0, {%1, %2};" : "=l"(r) : "f"(lo), "f"(hi));
    return r;
}
__device__ __forceinline__ void fma2(unsigned long long& d,
                                     unsigned long long a,
                                     unsigned long long b) {
    asm("fma.rn.f32x2 %0, %1, %2, %0;" : "+l"(d) : "l"(a), "l"(b));
}
__device__ __forceinline__ void unpack2(unsigned long long v, float& lo, float& hi) {
    asm("mov.b64 {%0, %1}, %2;" : "=f"(lo), "=f"(hi) : "l"(v));
}

// ---------------- K_zero: zero the whole output buffer ----------------
__global__ void k_zero(float* __restrict__ out, long long n_elem) {
    long long n4 = n_elem >> 2;
    float4 z = make_float4(0.f, 0.f, 0.f, 0.f);
    float4* o = reinterpret_cast<float4*>(out);
    long long stride = (long long)gridDim.x * blockDim.x;
    for (long long i = (long long)blockIdx.x * blockDim.x + threadIdx.x; i < n4; i += stride)
        o[i] = z;
    if (blockIdx.x == 0 && threadIdx.x == 0)
        for (long long r = n4 << 2; r < n_elem; r++) out[r] = 0.f;
}

// ---------------- K_prep1: Wp[r] = dot(W[r,:], p)  (warp per row, coalesced) ----------------
__global__ void k_prep1(const float* __restrict__ W, const float* __restrict__ p) {
    __shared__ float ps[CC];
    int tid = threadIdx.x;              // 256
    ps[tid] = p[tid];
    __syncthreads();
    int warp = tid >> 5, lane = tid & 31;
    int r = blockIdx.x * 8 + warp;      // 32 blocks x 8 warps = 256 rows
    const float* wr = W + (size_t)r * CC;
    float acc = 0.f;
#pragma unroll
    for (int j = lane; j < CC; j += 32) acc += wr[j] * ps[j];
    for (int o = 16; o > 0; o >>= 1) acc += __shfl_down_sync(0xffffffffu, acc, o);
    if (lane == 0) g_Wp[r] = acc;
}

// ---------------- K_prep2: 1/||p|| and b.p ----------------
__global__ void k_prep2(const float* __restrict__ b, const float* __restrict__ p) {
    __shared__ float s1[CC], s2[CC];
    int c = threadIdx.x;
    float pc = p[c];
    s1[c] = pc * pc;
    s2[c] = b[c] * pc;
    __syncthreads();
    for (int off = CC / 2; off > 0; off >>= 1) {
        if (c < off) { s1[c] += s1[c + off]; s2[c] += s2[c + off]; }
        __syncthreads();
    }
    if (c == 0) {
        g_scal[0] = 1.0f / sqrtf(s1[0]);
        g_scal[1] = s2[0];
    }
}

// ---------------- K_t: t[b,n] = x[b,n,:] . Wp  (warp per row) ----------------
__global__ void k_t(const float* __restrict__ x) {
    __shared__ float wp[CC];
    int tid = threadIdx.x;
    wp[tid] = g_Wp[tid];
    __syncthreads();
    int warp = tid >> 5, lane = tid & 31;
    int row = blockIdx.x * 8 + warp;           // [0, BB*NN)
    const float* xr = x + (size_t)row * CC;
    float acc = 0.f;
#pragma unroll 4
    for (int j = lane; j < CC; j += 32) acc += xr[j] * wp[j];
    for (int o = 16; o > 0; o >>= 1) acc += __shfl_down_sync(0xffffffffu, acc, o);
    if (lane == 0) g_t[row] = acc;
}

// ---------------- K_adjscan: one float4 pass over adj -> y scores + nnz lists ----------------
__global__ void k_adjscan(const float* __restrict__ adj) {
    __shared__ float s[NN];
    int tid = threadIdx.x;
    int b = blockIdx.x >> 7;           // 128 blocks per batch
    int chunk = blockIdx.x & 127;
    for (int i = tid; i < NN; i += blockDim.x) s[i] = g_t[b * NN + i];
    __syncthreads();
    int warp = tid >> 5, lane = tid & 31;
    int n = chunk * 8 + warp;
    const float* ar = adj + ((size_t)b * NN + n) * NN;
    unsigned short* ir = g_idx + ((size_t)b * NN + n) * NN;
    float acc = 0.f;
    int cnt = 0;
    // NOTE: indices within each 128-col chunk are emitted in stride-4-class order,
    // not column order. Consumers (gather sum, adjout scatter) are order-agnostic.
    for (int m0 = 0; m0 < NN; m0 += 128) {
        float4 v = *(const float4*)(ar + m0 + lane * 4);
        float4 sv = *(const float4*)(&s[m0 + lane * 4]);
        acc += v.x * sv.x + v.y * sv.y;
        acc += v.z * sv.z + v.w * sv.w;
        float vv[4] = {v.x, v.y, v.z, v.w};
#pragma unroll
        for (int u = 0; u < 4; u++) {
            unsigned ball = __ballot_sync(0xffffffffu, vv[u] != 0.0f);
            if (vv[u] != 0.0f) {
                int pos = cnt + __popc(ball & ((1u << lane) - 1u));
                ir[pos] = (unsigned short)(m0 + lane * 4 + u);
            }
            cnt += __popc(ball);
        }
    }
    for (int o = 16; o > 0; o >>= 1) acc += __shfl_down_sync(0xffffffffu, acc, o);
    if (lane == 0) {
        g_cnt[b * NN + n] = cnt;
        g_y[b * NN + n] = (acc + g_scal[1]) * g_scal[0];
    }
}

// ---------------- K_rank: pairwise stable ranking (8 sub-threads per i) ----------------
__global__ void k_rank(const int* __restrict__ mask,
                       const int* __restrict__ n_nodes,
                       float* __restrict__ out_mask) {
    int b = blockIdx.y;
    __shared__ float ys[NN];
    __shared__ int   ms[NN];
    int t = threadIdx.x;               // 1024
    ys[t] = g_y[b * NN + t];
    ms[t] = mask[b * NN + t];
    __syncthreads();
    int i   = blockIdx.x * 128 + (t >> 3);
    int sub = t & 7;
    float yi = ys[i];
    int r = 0;
    int j0 = sub * 128;
#pragma unroll 4
    for (int j = j0; j < j0 + 128; j++) {
        float yj = ys[j];
        if ((yj < yi || (yj == yi && j < i)) && ms[j]) r++;
    }
    r += __shfl_down_sync(0xffffffffu, r, 4, 8);
    r += __shfl_down_sync(0xffffffffu, r, 2, 8);
    r += __shfl_down_sync(0xffffffffu, r, 1, 8);
    if (sub == 0) {
        int mi = ms[i];
        int nrem = (int)((float)n_nodes[b] * 0.5f);   // (1 - POOL_RATIO)
        int nm = (mi != 0 && r >= nrem) ? 1 : 0;
        g_mf[b * NN + i] = (float)nm;
        out_mask[b * NN + i] = (float)nm;
    }
}

// ---------------- K_compact: per-batch scan -> compact surviving row list ----------------
__global__ void k_compact(const int* __restrict__ n_nodes, float* __restrict__ out_nn) {
    int b = blockIdx.x;
    int i = threadIdx.x;
    __shared__ int sc[NN];
    int nm = (int)g_mf[b * NN + i];
    sc[i] = nm;
    __syncthreads();
    for (int off = 1; off < NN; off <<= 1) {
        int v = (i >= off) ? sc[i - off] : 0;
        __syncthreads();
        sc[i] += v;
        __syncthreads();
    }
    int excl = sc[i] - nm;
    if (nm) g_rows[b * NN + excl] = i;
    if (i == 0) {
        g_nrows[b] = sc[NN - 1];
        int nrem = (int)((float)n_nodes[b] * 0.5f);
        out_nn[b] = (float)(n_nodes[b] - nrem);
    }
}

// ---------------- K_gather: g_gc[compact row] = sum of x rows over nnz ----------------
__global__ void k_gather(const float* __restrict__ x) {
    int b = blockIdx.y;
    int pos = blockIdx.x;
    if (pos >= g_nrows[b]) return;
    int row = g_rows[b * NN + pos];
    int cnt = g_cnt[b * NN + row];
    __shared__ unsigned short sidx[NN];
    const unsigned short* ir = g_idx + ((size_t)b * NN + row) * NN;
    for (int t = threadIdx.x; t < cnt; t += blockDim.x) sidx[t] = ir[t];
    __syncthreads();
    int c = threadIdx.x;
    const float* xb = x + (size_t)b * NN * CC;
    float a0 = 0.f, a1 = 0.f, a2 = 0.f, a3 = 0.f;
    int t = 0;
    for (; t + 4 <= cnt; t += 4) {
        a0 += xb[(int)sidx[t + 0] * CC + c];
        a1 += xb[(int)sidx[t + 1] * CC + c];
        a2 += xb[(int)sidx[t + 2] * CC + c];
        a3 += xb[(int)sidx[t + 3] * CC + c];
    }
    for (; t < cnt; t++) a0 += xb[(int)sidx[t] * CC + c];
    g_gc[((size_t)b * NN + pos) * CC + c] = (a0 + a1) + (a2 + a3);
}

// ---------------- K_gemm: x_out[masked rows] = (g_gc @ W + b) * tanh(y) ----------------
#define GM 128
#define GN 128
#define GK 16

__global__ __launch_bounds__(256) void k_gemm(const float* __restrict__ W,
                                              const float* __restrict__ bvec,
                                              float* __restrict__ out_x) {
    int b = blockIdx.z;
    int nrows = g_nrows[b];
    int row0 = blockIdx.x * GM;
    if (row0 >= nrows) return;
    int col0 = blockIdx.y * GN;
    int rows_in = nrows - row0;
    if (rows_in > GM) rows_in = GM;

    __shared__ float As[2][GK][GM + 4];
    __shared__ float Bs[2][GK][GN];

    const float* A = g_gc + ((size_t)b * NN + row0) * CC;
    int tid = threadIdx.x;
    int tx = tid & 15;   // row group: rows tx*8 .. tx*8+7
    int ty = tid >> 4;   // col group: cols ty*8 .. ty*8+7

    unsigned long long acc[8][4];
#pragma unroll
    for (int i = 0; i < 8; i++)
#pragma unroll
        for (int j = 0; j < 4; j++) acc[i][j] = 0ULL;  // bits == (0.f, 0.f)

    float4 ra[2], rb[2];

#define LOAD_A(kt)                                                              \
    {                                                                           \
        _Pragma("unroll") for (int u = 0; u < 2; u++) {                         \
            int idx = tid + u * 256;                                            \
            int m = idx >> 2, k4 = idx & 3;                                     \
            ra[u] = (m < rows_in)                                               \
                        ? *(const float4*)(A + (size_t)m * CC + (kt) + k4 * 4)  \
                        : make_float4(0.f, 0.f, 0.f, 0.f);                      \
        }                                                                       \
    }
#define LOAD_B(kt)                                                              \
    {                                                                           \
        _Pragma("unroll") for (int u = 0; u < 2; u++) {                         \
            int idx = tid + u * 256;                                            \
            int k = idx >> 5, c4 = idx & 31;                                    \
            rb[u] = *(const float4*)(W + (size_t)((kt) + k) * CC + col0 + c4 * 4); \
        }                                                                       \
    }
#define STORE_AB(buf)                                                           \
    {                                                                           \
        _Pragma("unroll") for (int u = 0; u < 2; u++) {                         \
            int idx = tid + u * 256;                                            \
            int m = idx >> 2, k4 = idx & 3;                                     \
            As[buf][k4 * 4 + 0][m] = ra[u].x;                                   \
            As[buf][k4 * 4 + 1][m] = ra[u].y;                                   \
            As[buf][k4 * 4 + 2][m] = ra[u].z;                                   \
            As[buf][k4 * 4 + 3][m] = ra[u].w;                                   \
            int k = idx >> 5, c4 = idx & 31;                                    \
            *(float4*)&Bs[buf][k][c4 * 4] = rb[u];                              \
        }                                                                       \
    }

    LOAD_A(0)
    LOAD_B(0)
    STORE_AB(0)
    __syncthreads();

    int buf = 0;
    for (int kt = 0; kt < CC; kt += GK) {
        if (kt + GK < CC) {
            LOAD_A(kt + GK)
            LOAD_B(kt + GK)
        }
#pragma unroll
        for (int k = 0; k < GK; k++) {
            float af[8], bf[8];
            *(float4*)&af[0] = *(const float4*)&As[buf][k][tx * 8];
            *(float4*)&af[4] = *(const float4*)&As[buf][k][tx * 8 + 4];
            *(float4*)&bf[0] = *(const float4*)&Bs[buf][k][ty * 8];
            *(float4*)&bf[4] = *(const float4*)&Bs[buf][k][ty * 8 + 4];
            unsigned long long b2[4];
#pragma unroll
            for (int j = 0; j < 4; j++) b2[j] = pack2(bf[2 * j], bf[2 * j + 1]);
#pragma unroll
            for (int i = 0; i < 8; i++) {
                unsigned long long a2 = pack2(af[i], af[i]);
#pragma unroll
                for (int j = 0; j < 4; j++) fma2(acc[i][j], a2, b2[j]);
            }
        }
        if (kt + GK < CC) {
            STORE_AB(buf ^ 1)
        }
        __syncthreads();
        buf ^= 1;
    }

    // epilogue: scatter rows to their original node positions with bias + tanh scale
#pragma unroll
    for (int i = 0; i < 8; i++) {
        int m = tx * 8 + i;
        if (row0 + m < nrows) {
            int n = g_rows[b * NN + row0 + m];
            float tval = tanhf(g_y[b * NN + n]);
            float res[8];
#pragma unroll
            for (int j = 0; j < 4; j++) unpack2(acc[i][j], res[2 * j], res[2 * j + 1]);
#pragma unroll
            for (int j = 0; j < 8; j++)
                res[j] = (res[j] + bvec[col0 + ty * 8 + j]) * tval;
            float* orow = out_x + ((size_t)b * NN + n) * CC + col0 + ty * 8;
            *(float4*)&orow[0] = *(float4*)&res[0];
            *(float4*)&orow[4] = *(float4*)&res[4];
        }
    }
#undef LOAD_A
#undef LOAD_B
#undef STORE_AB
}

// ---------------- K_adjout: scatter 1.0 at surviving nnz positions ----------------
__global__ void k_adjout(float* __restrict__ out_adj) {
    int b = blockIdx.y;
    int pos = blockIdx.x;
    if (pos >= g_nrows[b]) return;
    int n = g_rows[b * NN + pos];
    int cnt = g_cnt[b * NN + n];
    const unsigned short* ir = g_idx + ((size_t)b * NN + n) * NN;
    float* orow = out_adj + ((size_t)b * NN + n) * NN;
    for (int t = threadIdx.x; t < cnt; t += blockDim.x) {
        int m = ir[t];
        if (g_mf[b * NN + m] != 0.0f) orow[m] = 1.0f;
    }
}

// ---------------- launch ----------------
extern "C" void kernel_launch(void* const* d_in, const int* in_sizes, int n_in,
                              void* d_out, int out_size) {
    const float* x    = (const float*)d_in[0];  // [B,N,C]
    const float* adj  = (const float*)d_in[1];  // [B,N,N]
    const int*   mask = (const int*)d_in[2];    // [B,N]
    const int*   nnod = (const int*)d_in[3];    // [B]
    const float* W    = (const float*)d_in[4];  // [C,C]
    const float* bv   = (const float*)d_in[5];  // [C]
    const float* pool = (const float*)d_in[6];  // [C,1]

    float* out = (float*)d_out;
    float* out_x    = out;                                   // B*N*C
    float* out_adj  = out + (size_t)BB * NN * CC;            // B*N*N
    float* out_mask = out_adj + (size_t)BB * NN * NN;        // B*N
    float* out_nn   = out_mask + (size_t)BB * NN;            // B

    k_zero<<<4096, 256>>>(out, (long long)out_size);
    k_prep1<<<32, 256>>>(W, pool);
    k_prep2<<<1, 256>>>(bv, pool);
    k_t<<<(BB * NN) / 8, 256>>>(x);
    k_adjscan<<<(BB * NN) / 8, 256>>>(adj);
    k_rank<<<dim3(8, BB), 1024>>>(mask, nnod, out_mask);
    k_compact<<<BB, 1024>>>(nnod, out_nn);
    k_gather<<<dim3(NN, BB), CC>>>(x);
    k_gemm<<<dim3(NN / GM, CC / GN, BB), 256>>>(W, bv, out_x);
    k_adjout<<<dim3(NN, BB), 64>>>(out_adj);
}

// round 4
// speedup vs baseline: 1.3003x; 1.1108x over previous
#include <cuda_runtime.h>
#include <cstdint>
#include <math.h>

#define BB 16
#define NN 1024
#define CC 256

// ---------------- scratch (__device__ globals: allocation-free) ----------------
__device__ float          g_Wp[CC];            // W @ pooling  (row dots)
__device__ float          g_scal[2];           // [0] = 1/||p||, [1] = b.p
__device__ float          g_t[BB * NN];        // x . Wp  per node
__device__ float          g_y[BB * NN];        // scores
__device__ float          g_mf[BB * NN];       // new mask (float)
__device__ int            g_cnt[BB * NN];      // nnz per adj row
__device__ unsigned short g_idx[(size_t)BB * NN * NN]; // nnz col indices per row
__device__ int            g_rows[BB * NN];     // compacted surviving node ids per batch
__device__ int            g_dead[BB * NN];     // compacted dead node ids per batch
__device__ int            g_nrows[BB];         // surviving count per batch
__device__ int            g_ndead[BB];         // dead count per batch
__device__ float          g_gc[(size_t)BB * NN * CC];  // gathered sums, compact (16 MB)

// ---------------- f32x2 helpers (sm_103a packed fp32 FMA) ----------------
__device__ __forceinline__ unsigned long long pack2(float lo, float hi) {
    unsigned long long r;
    asm("mov.b64 %0, {%1, %2};" : "=l"(r) : "f"(lo), "f"(hi));
    return r;
}
__device__ __forceinline__ void fma2(unsigned long long& d,
                                     unsigned long long a,
                                     unsigned long long b) {
    asm("fma.rn.f32x2 %0, %1, %2, %0;" : "+l"(d) : "l"(a), "l"(b));
}
__device__ __forceinline__ void unpack2(unsigned long long v, float& lo, float& hi) {
    asm("mov.b64 {%0, %1}, %2;" : "=f"(lo), "=f"(hi) : "l"(v));
}

// ---------------- K_prep: blocks 0..31: Wp rows; block 32: scal ----------------
__global__ void k_prep(const float* __restrict__ W,
                       const float* __restrict__ b,
                       const float* __restrict__ p) {
    int tid = threadIdx.x;  // 256
    if (blockIdx.x == 32) {
        __shared__ float s1[CC], s2[CC];
        float pc = p[tid];
        s1[tid] = pc * pc;
        s2[tid] = b[tid] * pc;
        __syncthreads();
        for (int off = CC / 2; off > 0; off >>= 1) {
            if (tid < off) { s1[tid] += s1[tid + off]; s2[tid] += s2[tid + off]; }
            __syncthreads();
        }
        if (tid == 0) {
            g_scal[0] = 1.0f / sqrtf(s1[0]);
            g_scal[1] = s2[0];
        }
        return;
    }
    __shared__ float ps[CC];
    ps[tid] = p[tid];
    __syncthreads();
    int warp = tid >> 5, lane = tid & 31;
    int r = blockIdx.x * 8 + warp;
    const float* wr = W + (size_t)r * CC;
    float acc = 0.f;
#pragma unroll
    for (int j = lane; j < CC; j += 32) acc += wr[j] * ps[j];
    for (int o = 16; o > 0; o >>= 1) acc += __shfl_down_sync(0xffffffffu, acc, o);
    if (lane == 0) g_Wp[r] = acc;
}

// ---------------- K_t: t[b,n] = x[b,n,:] . Wp  (warp per row, float4) ----------------
__global__ void k_t(const float* __restrict__ x) {
    __shared__ float4 wp4[CC / 4];
    int tid = threadIdx.x;  // 256
    if (tid < CC / 4) wp4[tid] = ((const float4*)g_Wp)[tid];
    __syncthreads();
    int warp = tid >> 5, lane = tid & 31;
    int row = blockIdx.x * 8 + warp;           // [0, BB*NN)
    const float4* xr = (const float4*)(x + (size_t)row * CC);
    float4 v0 = xr[lane];
    float4 v1 = xr[lane + 32];
    float4 w0 = wp4[lane];
    float4 w1 = wp4[lane + 32];
    float acc = v0.x * w0.x + v0.y * w0.y + v0.z * w0.z + v0.w * w0.w
              + v1.x * w1.x + v1.y * w1.y + v1.z * w1.z + v1.w * w1.w;
    for (int o = 16; o > 0; o >>= 1) acc += __shfl_down_sync(0xffffffffu, acc, o);
    if (lane == 0) g_t[row] = acc;
}

// ---------------- K_adjscan: one float4 pass over adj -> y scores + nnz lists ----------------
__global__ void k_adjscan(const float* __restrict__ adj) {
    __shared__ float s[NN];
    int tid = threadIdx.x;
    int b = blockIdx.x >> 7;           // 128 blocks per batch
    int chunk = blockIdx.x & 127;
    for (int i = tid; i < NN; i += blockDim.x) s[i] = g_t[b * NN + i];
    __syncthreads();
    int warp = tid >> 5, lane = tid & 31;
    int n = chunk * 8 + warp;
    const float* ar = adj + ((size_t)b * NN + n) * NN;
    unsigned short* ir = g_idx + ((size_t)b * NN + n) * NN;
    float acc = 0.f;
    int cnt = 0;
    for (int m0 = 0; m0 < NN; m0 += 128) {
        float4 v = *(const float4*)(ar + m0 + lane * 4);
        float4 sv = *(const float4*)(&s[m0 + lane * 4]);
        acc += v.x * sv.x + v.y * sv.y;
        acc += v.z * sv.z + v.w * sv.w;
        float vv[4] = {v.x, v.y, v.z, v.w};
#pragma unroll
        for (int u = 0; u < 4; u++) {
            unsigned ball = __ballot_sync(0xffffffffu, vv[u] != 0.0f);
            if (vv[u] != 0.0f) {
                int pos = cnt + __popc(ball & ((1u << lane) - 1u));
                ir[pos] = (unsigned short)(m0 + lane * 4 + u);
            }
            cnt += __popc(ball);
        }
    }
    for (int o = 16; o > 0; o >>= 1) acc += __shfl_down_sync(0xffffffffu, acc, o);
    if (lane == 0) {
        g_cnt[b * NN + n] = cnt;
        g_y[b * NN + n] = (acc + g_scal[1]) * g_scal[0];
    }
}

// ---------------- K_rank: pairwise stable ranking (8 sub-threads per i) ----------------
__global__ void k_rank(const int* __restrict__ mask,
                       const int* __restrict__ n_nodes,
                       float* __restrict__ out_mask) {
    int b = blockIdx.y;
    __shared__ float ys[NN];
    __shared__ int   ms[NN];
    int t = threadIdx.x;               // 1024
    ys[t] = g_y[b * NN + t];
    ms[t] = mask[b * NN + t];
    __syncthreads();
    int i   = blockIdx.x * 128 + (t >> 3);
    int sub = t & 7;
    float yi = ys[i];
    int r = 0;
    int j0 = sub * 128;
#pragma unroll 4
    for (int j = j0; j < j0 + 128; j++) {
        float yj = ys[j];
        if ((yj < yi || (yj == yi && j < i)) && ms[j]) r++;
    }
    r += __shfl_down_sync(0xffffffffu, r, 4, 8);
    r += __shfl_down_sync(0xffffffffu, r, 2, 8);
    r += __shfl_down_sync(0xffffffffu, r, 1, 8);
    if (sub == 0) {
        int mi = ms[i];
        int nrem = (int)((float)n_nodes[b] * 0.5f);   // (1 - POOL_RATIO)
        int nm = (mi != 0 && r >= nrem) ? 1 : 0;
        g_mf[b * NN + i] = (float)nm;
        out_mask[b * NN + i] = (float)nm;
    }
}

// ---------------- K_compact: warp-scan -> surviving + dead node lists ----------------
__global__ void k_compact(const int* __restrict__ n_nodes, float* __restrict__ out_nn) {
    int b = blockIdx.x;
    int i = threadIdx.x;               // 1024
    int lane = i & 31, w = i >> 5;
    int nm = (int)g_mf[b * NN + i];
    unsigned ball = __ballot_sync(0xffffffffu, nm != 0);
    int wpre = __popc(ball & ((1u << lane) - 1u));
    __shared__ int wsum[32];
    if (lane == 0) wsum[w] = __popc(ball);
    __syncthreads();
    if (w == 0) {
        int orig = wsum[lane];
        int v = orig;
        for (int o = 1; o < 32; o <<= 1) {
            int u = __shfl_up_sync(0xffffffffu, v, o);
            if (lane >= o) v += u;
        }
        wsum[lane] = v - orig;   // exclusive
    }
    __syncthreads();
    int excl = wsum[w] + wpre;
    if (nm) g_rows[b * NN + excl] = i;
    else    g_dead[b * NN + (i - excl)] = i;
    if (i == NN - 1) {
        int tot = excl + nm;
        g_nrows[b] = tot;
        g_ndead[b] = NN - tot;
        int nrem = (int)((float)n_nodes[b] * 0.5f);
        out_nn[b] = (float)(n_nodes[b] - nrem);
    }
}

// ---------------- K_zero_dead: zero x_out rows of dead nodes ----------------
__global__ void k_zero_dead(float* __restrict__ out_x) {
    int b = blockIdx.y;
    int pos = blockIdx.x;
    if (pos >= g_ndead[b]) return;
    int n = g_dead[b * NN + pos];
    float4* orow = (float4*)(out_x + ((size_t)b * NN + n) * CC);
    orow[threadIdx.x] = make_float4(0.f, 0.f, 0.f, 0.f);   // 64 threads x 16B = 1KB
}

// ---------------- K_gather: 4 rows per block, float4 channels ----------------
__global__ __launch_bounds__(256) void k_gather(const float* __restrict__ x) {
    int b = blockIdx.y;
    int nrows = g_nrows[b];
    if (blockIdx.x * 4 >= nrows) return;
    int tid = threadIdx.x;
    int sub = tid >> 6;        // row within block
    int ct  = tid & 63;        // float4 channel group
    int pos = blockIdx.x * 4 + sub;
    bool active = pos < nrows;

    __shared__ unsigned short sidx[4][128];
    int row = 0, cnt = 0;
    const unsigned short* ir = nullptr;
    if (active) {
        row = g_rows[b * NN + pos];
        cnt = g_cnt[b * NN + row];
        ir  = g_idx + ((size_t)b * NN + row) * NN;
        int lim = cnt < 128 ? cnt : 128;
        for (int t = ct; t < lim; t += 64) sidx[sub][t] = ir[t];
    }
    __syncthreads();
    if (!active) return;

    const float* xb = x + (size_t)b * NN * CC + ct * 4;
    float4 a0 = make_float4(0.f, 0.f, 0.f, 0.f);
    float4 a1 = make_float4(0.f, 0.f, 0.f, 0.f);
    int t = 0;
    for (; t + 2 <= cnt && t + 2 <= 128; t += 2) {
        float4 v0 = *(const float4*)(xb + (int)sidx[sub][t] * CC);
        float4 v1 = *(const float4*)(xb + (int)sidx[sub][t + 1] * CC);
        a0.x += v0.x; a0.y += v0.y; a0.z += v0.z; a0.w += v0.w;
        a1.x += v1.x; a1.y += v1.y; a1.z += v1.z; a1.w += v1.w;
    }
    for (; t < cnt; t++) {
        int idx = (t < 128) ? (int)sidx[sub][t] : (int)ir[t];
        float4 v = *(const float4*)(xb + idx * CC);
        a0.x += v.x; a0.y += v.y; a0.z += v.z; a0.w += v.w;
    }
    float4 r;
    r.x = a0.x + a1.x; r.y = a0.y + a1.y; r.z = a0.z + a1.z; r.w = a0.w + a1.w;
    *(float4*)(g_gc + ((size_t)b * NN + pos) * CC + ct * 4) = r;
}

// ---------------- K_gemm: x_out[surviving rows] = (g_gc @ W + b) * tanh(y) ----------------
#define GM 128
#define GN 128
#define GK 16

__global__ __launch_bounds__(256) void k_gemm(const float* __restrict__ W,
                                              const float* __restrict__ bvec,
                                              float* __restrict__ out_x) {
    int b = blockIdx.z;
    int nrows = g_nrows[b];
    int row0 = blockIdx.x * GM;
    if (row0 >= nrows) return;
    int col0 = blockIdx.y * GN;
    int rows_in = nrows - row0;
    if (rows_in > GM) rows_in = GM;

    __shared__ float As[2][GK][GM + 4];
    __shared__ float Bs[2][GK][GN];

    const float* A = g_gc + ((size_t)b * NN + row0) * CC;
    int tid = threadIdx.x;
    int tx = tid & 15;   // row group
    int ty = tid >> 4;   // col group

    unsigned long long acc[8][4];
#pragma unroll
    for (int i = 0; i < 8; i++)
#pragma unroll
        for (int j = 0; j < 4; j++) acc[i][j] = 0ULL;

    float4 ra[2], rb[2];

#define LOAD_A(kt)                                                              \
    {                                                                           \
        _Pragma("unroll") for (int u = 0; u < 2; u++) {                         \
            int idx = tid + u * 256;                                            \
            int m = idx >> 2, k4 = idx & 3;                                     \
            ra[u] = (m < rows_in)                                               \
                        ? *(const float4*)(A + (size_t)m * CC + (kt) + k4 * 4)  \
                        : make_float4(0.f, 0.f, 0.f, 0.f);                      \
        }                                                                       \
    }
#define LOAD_B(kt)                                                              \
    {                                                                           \
        _Pragma("unroll") for (int u = 0; u < 2; u++) {                         \
            int idx = tid + u * 256;                                            \
            int k = idx >> 5, c4 = idx & 31;                                    \
            rb[u] = *(const float4*)(W + (size_t)((kt) + k) * CC + col0 + c4 * 4); \
        }                                                                       \
    }
#define STORE_AB(buf)                                                           \
    {                                                                           \
        _Pragma("unroll") for (int u = 0; u < 2; u++) {                         \
            int idx = tid + u * 256;                                            \
            int m = idx >> 2, k4 = idx & 3;                                     \
            As[buf][k4 * 4 + 0][m] = ra[u].x;                                   \
            As[buf][k4 * 4 + 1][m] = ra[u].y;                                   \
            As[buf][k4 * 4 + 2][m] = ra[u].z;                                   \
            As[buf][k4 * 4 + 3][m] = ra[u].w;                                   \
            int k = idx >> 5, c4 = idx & 31;                                    \
            *(float4*)&Bs[buf][k][c4 * 4] = rb[u];                              \
        }                                                                       \
    }

    LOAD_A(0)
    LOAD_B(0)
    STORE_AB(0)
    __syncthreads();

    int buf = 0;
    for (int kt = 0; kt < CC; kt += GK) {
        if (kt + GK < CC) {
            LOAD_A(kt + GK)
            LOAD_B(kt + GK)
        }
#pragma unroll
        for (int k = 0; k < GK; k++) {
            float af[8], bf[8];
            *(float4*)&af[0] = *(const float4*)&As[buf][k][tx * 8];
            *(float4*)&af[4] = *(const float4*)&As[buf][k][tx * 8 + 4];
            *(float4*)&bf[0] = *(const float4*)&Bs[buf][k][ty * 8];
            *(float4*)&bf[4] = *(const float4*)&Bs[buf][k][ty * 8 + 4];
            unsigned long long b2[4];
#pragma unroll
            for (int j = 0; j < 4; j++) b2[j] = pack2(bf[2 * j], bf[2 * j + 1]);
#pragma unroll
            for (int i = 0; i < 8; i++) {
                unsigned long long a2 = pack2(af[i], af[i]);
#pragma unroll
                for (int j = 0; j < 4; j++) fma2(acc[i][j], a2, b2[j]);
            }
        }
        if (kt + GK < CC) {
            STORE_AB(buf ^ 1)
        }
        __syncthreads();
        buf ^= 1;
    }

#pragma unroll
    for (int i = 0; i < 8; i++) {
        int m = tx * 8 + i;
        if (row0 + m < nrows) {
            int n = g_rows[b * NN + row0 + m];
            float tval = tanhf(g_y[b * NN + n]);
            float res[8];
#pragma unroll
            for (int j = 0; j < 4; j++) unpack2(acc[i][j], res[2 * j], res[2 * j + 1]);
#pragma unroll
            for (int j = 0; j < 8; j++)
                res[j] = (res[j] + bvec[col0 + ty * 8 + j]) * tval;
            float* orow = out_x + ((size_t)b * NN + n) * CC + col0 + ty * 8;
            *(float4*)&orow[0] = *(float4*)&res[0];
            *(float4*)&orow[4] = *(float4*)&res[4];
        }
    }
#undef LOAD_A
#undef LOAD_B
#undef STORE_AB
}

// ---------------- K_adjout: dense adj_out rows (zeros or expanded nnz) ----------------
__global__ __launch_bounds__(256) void k_adjout(float* __restrict__ out_adj) {
    int b = blockIdx.y;
    int n = blockIdx.x;
    int tid = threadIdx.x;  // 256
    float4* orow = (float4*)(out_adj + ((size_t)b * NN + n) * NN);
    if (g_mf[b * NN + n] == 0.0f) {
        orow[tid] = make_float4(0.f, 0.f, 0.f, 0.f);    // 256 x 16B = 4KB
        return;
    }
    __shared__ float srow[NN];
    *(float4*)&srow[tid * 4] = make_float4(0.f, 0.f, 0.f, 0.f);
    __syncthreads();
    int cnt = g_cnt[b * NN + n];
    const unsigned short* ir = g_idx + ((size_t)b * NN + n) * NN;
    for (int t = tid; t < cnt; t += 256) {
        int m = ir[t];
        if (g_mf[b * NN + m] != 0.0f) srow[m] = 1.0f;
    }
    __syncthreads();
    orow[tid] = *(float4*)&srow[tid * 4];
}

// ---------------- launch ----------------
extern "C" void kernel_launch(void* const* d_in, const int* in_sizes, int n_in,
                              void* d_out, int out_size) {
    const float* x    = (const float*)d_in[0];  // [B,N,C]
    const float* adj  = (const float*)d_in[1];  // [B,N,N]
    const int*   mask = (const int*)d_in[2];    // [B,N]
    const int*   nnod = (const int*)d_in[3];    // [B]
    const float* W    = (const float*)d_in[4];  // [C,C]
    const float* bv   = (const float*)d_in[5];  // [C]
    const float* pool = (const float*)d_in[6];  // [C,1]

    float* out = (float*)d_out;
    float* out_x    = out;                                   // B*N*C
    float* out_adj  = out + (size_t)BB * NN * CC;            // B*N*N
    float* out_mask = out_adj + (size_t)BB * NN * NN;        // B*N
    float* out_nn   = out_mask + (size_t)BB * NN;            // B

    k_prep<<<33, 256>>>(W, bv, pool);
    k_t<<<(BB * NN) / 8, 256>>>(x);
    k_adjscan<<<(BB * NN) / 8, 256>>>(adj);
    k_rank<<<dim3(8, BB), 1024>>>(mask, nnod, out_mask);
    k_compact<<<BB, 1024>>>(nnod, out_nn);
    k_zero_dead<<<dim3(NN, BB), 64>>>(out_x);
    k_gather<<<dim3(NN / 4, BB), 256>>>(x);
    k_gemm<<<dim3(NN / GM, CC / GN, BB), 256>>>(W, bv, out_x);
    k_adjout<<<dim3(NN, BB), 256>>>(out_adj);
}

// round 5
// speedup vs baseline: 1.5377x; 1.1826x over previous
#include <cuda_runtime.h>
#include <cstdint>
#include <math.h>

#define BB 16
#define NN 1024
#define CC 256

// ---------------- scratch (__device__ globals: allocation-free) ----------------
__device__ float          g_Wp[CC];            // W @ pooling  (row dots)
__device__ float          g_scal[2];           // [0] = 1/||p||, [1] = b.p
__device__ float          g_t[BB * NN];        // x . Wp  per node
__device__ float          g_y[BB * NN];        // scores
__device__ float          g_mf[BB * NN];       // new mask (float)
__device__ int            g_cnt[BB * NN];      // nnz per adj row
__device__ unsigned short g_idx[(size_t)BB * NN * NN]; // nnz col indices per row
__device__ int            g_rows[BB * NN];     // compacted surviving node ids per batch
__device__ int            g_dead[BB * NN];     // compacted dead node ids per batch
__device__ int            g_nrows[BB];         // surviving count per batch
__device__ int            g_ndead[BB];         // dead count per batch
__device__ float          g_gc[(size_t)BB * NN * CC];  // gathered sums, compact (16 MB)

// ---------------- f32x2 helpers (sm_103a packed fp32 FMA) ----------------
__device__ __forceinline__ unsigned long long pack2(float lo, float hi) {
    unsigned long long r;
    asm("mov.b64 %0, {%1, %2};" : "=l"(r) : "f"(lo), "f"(hi));
    return r;
}
__device__ __forceinline__ void fma2(unsigned long long& d,
                                     unsigned long long a,
                                     unsigned long long b) {
    asm("fma.rn.f32x2 %0, %1, %2, %0;" : "+l"(d) : "l"(a), "l"(b));
}
__device__ __forceinline__ void unpack2(unsigned long long v, float& lo, float& hi) {
    asm("mov.b64 {%0, %1}, %2;" : "=f"(lo), "=f"(hi) : "l"(v));
}

// ---------------- K_prep: blocks 0..31: Wp rows; block 32: scal ----------------
__global__ void k_prep(const float* __restrict__ W,
                       const float* __restrict__ b,
                       const float* __restrict__ p) {
    int tid = threadIdx.x;  // 256
    if (blockIdx.x == 32) {
        __shared__ float s1[CC], s2[CC];
        float pc = p[tid];
        s1[tid] = pc * pc;
        s2[tid] = b[tid] * pc;
        __syncthreads();
        for (int off = CC / 2; off > 0; off >>= 1) {
            if (tid < off) { s1[tid] += s1[tid + off]; s2[tid] += s2[tid + off]; }
            __syncthreads();
        }
        if (tid == 0) {
            g_scal[0] = 1.0f / sqrtf(s1[0]);
            g_scal[1] = s2[0];
        }
        return;
    }
    __shared__ float ps[CC];
    ps[tid] = p[tid];
    __syncthreads();
    int warp = tid >> 5, lane = tid & 31;
    int r = blockIdx.x * 8 + warp;
    const float* wr = W + (size_t)r * CC;
    float acc = 0.f;
#pragma unroll
    for (int j = lane; j < CC; j += 32) acc += wr[j] * ps[j];
    for (int o = 16; o > 0; o >>= 1) acc += __shfl_down_sync(0xffffffffu, acc, o);
    if (lane == 0) g_Wp[r] = acc;
}

// ---------------- K_t: t[b,n] = x[b,n,:] . Wp  (warp per row, float4) ----------------
__global__ void k_t(const float* __restrict__ x) {
    __shared__ float4 wp4[CC / 4];
    int tid = threadIdx.x;  // 256
    if (tid < CC / 4) wp4[tid] = ((const float4*)g_Wp)[tid];
    __syncthreads();
    int warp = tid >> 5, lane = tid & 31;
    int row = blockIdx.x * 8 + warp;           // [0, BB*NN)
    const float4* xr = (const float4*)(x + (size_t)row * CC);
    float4 v0 = xr[lane];
    float4 v1 = xr[lane + 32];
    float4 w0 = wp4[lane];
    float4 w1 = wp4[lane + 32];
    float acc = v0.x * w0.x + v0.y * w0.y + v0.z * w0.z + v0.w * w0.w
              + v1.x * w1.x + v1.y * w1.y + v1.z * w1.z + v1.w * w1.w;
    for (int o = 16; o > 0; o >>= 1) acc += __shfl_down_sync(0xffffffffu, acc, o);
    if (lane == 0) g_t[row] = acc;
}

// ---------------- K_adjscan: one float4 pass over adj -> y scores + nnz lists ----------------
__global__ void k_adjscan(const float* __restrict__ adj) {
    __shared__ float s[NN];
    int tid = threadIdx.x;
    int b = blockIdx.x >> 7;           // 128 blocks per batch
    int chunk = blockIdx.x & 127;
    for (int i = tid; i < NN; i += blockDim.x) s[i] = g_t[b * NN + i];
    __syncthreads();
    int warp = tid >> 5, lane = tid & 31;
    int n = chunk * 8 + warp;
    const float* ar = adj + ((size_t)b * NN + n) * NN;
    unsigned short* ir = g_idx + ((size_t)b * NN + n) * NN;
    float acc = 0.f;
    int cnt = 0;
    for (int m0 = 0; m0 < NN; m0 += 128) {
        float4 v = *(const float4*)(ar + m0 + lane * 4);
        float4 sv = *(const float4*)(&s[m0 + lane * 4]);
        acc += v.x * sv.x + v.y * sv.y;
        acc += v.z * sv.z + v.w * sv.w;
        float vv[4] = {v.x, v.y, v.z, v.w};
#pragma unroll
        for (int u = 0; u < 4; u++) {
            unsigned ball = __ballot_sync(0xffffffffu, vv[u] != 0.0f);
            if (vv[u] != 0.0f) {
                int pos = cnt + __popc(ball & ((1u << lane) - 1u));
                ir[pos] = (unsigned short)(m0 + lane * 4 + u);
            }
            cnt += __popc(ball);
        }
    }
    for (int o = 16; o > 0; o >>= 1) acc += __shfl_down_sync(0xffffffffu, acc, o);
    if (lane == 0) {
        g_cnt[b * NN + n] = cnt;
        g_y[b * NN + n] = (acc + g_scal[1]) * g_scal[0];
    }
}

// ---------------- K_rank: pairwise stable ranking, conflict-free float4 LDS ----------------
// sub s covers j in {4s..4s+3} + 32k  (k=0..31): one LDS.128 per iter, 8 distinct
// float4 addresses per warp spanning all 32 banks (4-lane broadcast, no conflicts).
// Unmasked nodes are stored as +INF so they never count toward the rank.
__global__ void k_rank(const int* __restrict__ mask,
                       const int* __restrict__ n_nodes,
                       float* __restrict__ out_mask) {
    int b = blockIdx.y;
    __shared__ float ys[NN];
    int t = threadIdx.x;               // 1024
    int mt = mask[b * NN + t];
    float yv = g_y[b * NN + t];
    ys[t] = mt ? yv : __int_as_float(0x7f800000);  // +INF for unmasked
    __syncthreads();
    int i   = blockIdx.x * 128 + (t >> 3);
    int sub = t & 7;
    float yi = ys[i];
    const float4* ys4 = (const float4*)ys;
    int r = 0;
#pragma unroll 8
    for (int k = 0; k < 32; k++) {
        int f = sub + 8 * k;           // float4 chunk index
        float4 v = ys4[f];
        int j = f * 4;
        r += (v.x < yi || (v.x == yi && j     < i)) ? 1 : 0;
        r += (v.y < yi || (v.y == yi && j + 1 < i)) ? 1 : 0;
        r += (v.z < yi || (v.z == yi && j + 2 < i)) ? 1 : 0;
        r += (v.w < yi || (v.w == yi && j + 3 < i)) ? 1 : 0;
    }
    r += __shfl_down_sync(0xffffffffu, r, 4, 8);
    r += __shfl_down_sync(0xffffffffu, r, 2, 8);
    r += __shfl_down_sync(0xffffffffu, r, 1, 8);
    if (sub == 0) {
        int mi = mask[b * NN + i];
        int nrem = (int)((float)n_nodes[b] * 0.5f);   // (1 - POOL_RATIO)
        int nm = (mi != 0 && r >= nrem) ? 1 : 0;
        g_mf[b * NN + i] = (float)nm;
        out_mask[b * NN + i] = (float)nm;
    }
}

// ---------------- K_compact: warp-scan -> surviving + dead node lists ----------------
__global__ void k_compact(const int* __restrict__ n_nodes, float* __restrict__ out_nn) {
    int b = blockIdx.x;
    int i = threadIdx.x;               // 1024
    int lane = i & 31, w = i >> 5;
    int nm = (int)g_mf[b * NN + i];
    unsigned ball = __ballot_sync(0xffffffffu, nm != 0);
    int wpre = __popc(ball & ((1u << lane) - 1u));
    __shared__ int wsum[32];
    if (lane == 0) wsum[w] = __popc(ball);
    __syncthreads();
    if (w == 0) {
        int orig = wsum[lane];
        int v = orig;
        for (int o = 1; o < 32; o <<= 1) {
            int u = __shfl_up_sync(0xffffffffu, v, o);
            if (lane >= o) v += u;
        }
        wsum[lane] = v - orig;   // exclusive
    }
    __syncthreads();
    int excl = wsum[w] + wpre;
    if (nm) g_rows[b * NN + excl] = i;
    else    g_dead[b * NN + (i - excl)] = i;
    if (i == NN - 1) {
        int tot = excl + nm;
        g_nrows[b] = tot;
        g_ndead[b] = NN - tot;
        int nrem = (int)((float)n_nodes[b] * 0.5f);
        out_nn[b] = (float)(n_nodes[b] - nrem);
    }
}

// ---------------- K_zero_dead: zero x_out rows of dead nodes ----------------
__global__ void k_zero_dead(float* __restrict__ out_x) {
    int b = blockIdx.y;
    int pos = blockIdx.x;
    if (pos >= g_ndead[b]) return;
    int n = g_dead[b * NN + pos];
    float4* orow = (float4*)(out_x + ((size_t)b * NN + n) * CC);
    orow[threadIdx.x] = make_float4(0.f, 0.f, 0.f, 0.f);   // 64 threads x 16B = 1KB
}

// ---------------- K_gather: 4 rows per block, float4 channels ----------------
__global__ __launch_bounds__(256) void k_gather(const float* __restrict__ x) {
    int b = blockIdx.y;
    int nrows = g_nrows[b];
    if (blockIdx.x * 4 >= nrows) return;
    int tid = threadIdx.x;
    int sub = tid >> 6;        // row within block
    int ct  = tid & 63;        // float4 channel group
    int pos = blockIdx.x * 4 + sub;
    bool active = pos < nrows;

    __shared__ unsigned short sidx[4][128];
    int row = 0, cnt = 0;
    const unsigned short* ir = nullptr;
    if (active) {
        row = g_rows[b * NN + pos];
        cnt = g_cnt[b * NN + row];
        ir  = g_idx + ((size_t)b * NN + row) * NN;
        int lim = cnt < 128 ? cnt : 128;
        for (int t = ct; t < lim; t += 64) sidx[sub][t] = ir[t];
    }
    __syncthreads();
    if (!active) return;

    const float* xb = x + (size_t)b * NN * CC + ct * 4;
    float4 a0 = make_float4(0.f, 0.f, 0.f, 0.f);
    float4 a1 = make_float4(0.f, 0.f, 0.f, 0.f);
    int t = 0;
    for (; t + 2 <= cnt && t + 2 <= 128; t += 2) {
        float4 v0 = *(const float4*)(xb + (int)sidx[sub][t] * CC);
        float4 v1 = *(const float4*)(xb + (int)sidx[sub][t + 1] * CC);
        a0.x += v0.x; a0.y += v0.y; a0.z += v0.z; a0.w += v0.w;
        a1.x += v1.x; a1.y += v1.y; a1.z += v1.z; a1.w += v1.w;
    }
    for (; t < cnt; t++) {
        int idx = (t < 128) ? (int)sidx[sub][t] : (int)ir[t];
        float4 v = *(const float4*)(xb + idx * CC);
        a0.x += v.x; a0.y += v.y; a0.z += v.z; a0.w += v.w;
    }
    float4 r;
    r.x = a0.x + a1.x; r.y = a0.y + a1.y; r.z = a0.z + a1.z; r.w = a0.w + a1.w;
    *(float4*)(g_gc + ((size_t)b * NN + pos) * CC + ct * 4) = r;
}

// ---------------- K_gemm: x_out[surviving rows] = (g_gc @ W + b) * tanh(y) ----------------
#define GM 128
#define GN 128
#define GK 16

__global__ __launch_bounds__(256) void k_gemm(const float* __restrict__ W,
                                              const float* __restrict__ bvec,
                                              float* __restrict__ out_x) {
    int b = blockIdx.z;
    int nrows = g_nrows[b];
    int row0 = blockIdx.x * GM;
    if (row0 >= nrows) return;
    int col0 = blockIdx.y * GN;
    int rows_in = nrows - row0;
    if (rows_in > GM) rows_in = GM;

    __shared__ float As[2][GK][GM + 4];
    __shared__ float Bs[2][GK][GN];

    const float* A = g_gc + ((size_t)b * NN + row0) * CC;
    int tid = threadIdx.x;
    int tx = tid & 15;   // row group
    int ty = tid >> 4;   // col group

    unsigned long long acc[8][4];
#pragma unroll
    for (int i = 0; i < 8; i++)
#pragma unroll
        for (int j = 0; j < 4; j++) acc[i][j] = 0ULL;

    float4 ra[2], rb[2];

#define LOAD_A(kt)                                                              \
    {                                                                           \
        _Pragma("unroll") for (int u = 0; u < 2; u++) {                         \
            int idx = tid + u * 256;                                            \
            int m = idx >> 2, k4 = idx & 3;                                     \
            ra[u] = (m < rows_in)                                               \
                        ? *(const float4*)(A + (size_t)m * CC + (kt) + k4 * 4)  \
                        : make_float4(0.f, 0.f, 0.f, 0.f);                      \
        }                                                                       \
    }
#define LOAD_B(kt)                                                              \
    {                                                                           \
        _Pragma("unroll") for (int u = 0; u < 2; u++) {                         \
            int idx = tid + u * 256;                                            \
            int k = idx >> 5, c4 = idx & 31;                                    \
            rb[u] = *(const float4*)(W + (size_t)((kt) + k) * CC + col0 + c4 * 4); \
        }                                                                       \
    }
#define STORE_AB(buf)                                                           \
    {                                                                           \
        _Pragma("unroll") for (int u = 0; u < 2; u++) {                         \
            int idx = tid + u * 256;                                            \
            int m = idx >> 2, k4 = idx & 3;                                     \
            As[buf][k4 * 4 + 0][m] = ra[u].x;                                   \
            As[buf][k4 * 4 + 1][m] = ra[u].y;                                   \
            As[buf][k4 * 4 + 2][m] = ra[u].z;                                   \
            As[buf][k4 * 4 + 3][m] = ra[u].w;                                   \
            int k = idx >> 5, c4 = idx & 31;                                    \
            *(float4*)&Bs[buf][k][c4 * 4] = rb[u];                              \
        }                                                                       \
    }

    LOAD_A(0)
    LOAD_B(0)
    STORE_AB(0)
    __syncthreads();

    int buf = 0;
    for (int kt = 0; kt < CC; kt += GK) {
        if (kt + GK < CC) {
            LOAD_A(kt + GK)
            LOAD_B(kt + GK)
        }
#pragma unroll
        for (int k = 0; k < GK; k++) {
            float af[8], bf[8];
            *(float4*)&af[0] = *(const float4*)&As[buf][k][tx * 8];
            *(float4*)&af[4] = *(const float4*)&As[buf][k][tx * 8 + 4];
            *(float4*)&bf[0] = *(const float4*)&Bs[buf][k][ty * 8];
            *(float4*)&bf[4] = *(const float4*)&Bs[buf][k][ty * 8 + 4];
            unsigned long long b2[4];
#pragma unroll
            for (int j = 0; j < 4; j++) b2[j] = pack2(bf[2 * j], bf[2 * j + 1]);
#pragma unroll
            for (int i = 0; i < 8; i++) {
                unsigned long long a2 = pack2(af[i], af[i]);
#pragma unroll
                for (int j = 0; j < 4; j++) fma2(acc[i][j], a2, b2[j]);
            }
        }
        if (kt + GK < CC) {
            STORE_AB(buf ^ 1)
        }
        __syncthreads();
        buf ^= 1;
    }

#pragma unroll
    for (int i = 0; i < 8; i++) {
        int m = tx * 8 + i;
        if (row0 + m < nrows) {
            int n = g_rows[b * NN + row0 + m];
            float tval = tanhf(g_y[b * NN + n]);
            float res[8];
#pragma unroll
            for (int j = 0; j < 4; j++) unpack2(acc[i][j], res[2 * j], res[2 * j + 1]);
#pragma unroll
            for (int j = 0; j < 8; j++)
                res[j] = (res[j] + bvec[col0 + ty * 8 + j]) * tval;
            float* orow = out_x + ((size_t)b * NN + n) * CC + col0 + ty * 8;
            *(float4*)&orow[0] = *(float4*)&res[0];
            *(float4*)&orow[4] = *(float4*)&res[4];
        }
    }
#undef LOAD_A
#undef LOAD_B
#undef STORE_AB
}

// ---------------- K_adjout: dense adj_out rows (zeros or expanded nnz) ----------------
__global__ __launch_bounds__(256) void k_adjout(float* __restrict__ out_adj) {
    int b = blockIdx.y;
    int n = blockIdx.x;
    int tid = threadIdx.x;  // 256
    float4* orow = (float4*)(out_adj + ((size_t)b * NN + n) * NN);
    if (g_mf[b * NN + n] == 0.0f) {
        orow[tid] = make_float4(0.f, 0.f, 0.f, 0.f);    // 256 x 16B = 4KB
        return;
    }
    __shared__ float srow[NN];
    *(float4*)&srow[tid * 4] = make_float4(0.f, 0.f, 0.f, 0.f);
    __syncthreads();
    int cnt = g_cnt[b * NN + n];
    const unsigned short* ir = g_idx + ((size_t)b * NN + n) * NN;
    for (int t = tid; t < cnt; t += 256) {
        int m = ir[t];
        if (g_mf[b * NN + m] != 0.0f) srow[m] = 1.0f;
    }
    __syncthreads();
    orow[tid] = *(float4*)&srow[tid * 4];
}

// ---------------- launch ----------------
extern "C" void kernel_launch(void* const* d_in, const int* in_sizes, int n_in,
                              void* d_out, int out_size) {
    const float* x    = (const float*)d_in[0];  // [B,N,C]
    const float* adj  = (const float*)d_in[1];  // [B,N,N]
    const int*   mask = (const int*)d_in[2];    // [B,N]
    const int*   nnod = (const int*)d_in[3];    // [B]
    const float* W    = (const float*)d_in[4];  // [C,C]
    const float* bv   = (const float*)d_in[5];  // [C]
    const float* pool = (const float*)d_in[6];  // [C,1]

    float* out = (float*)d_out;
    float* out_x    = out;                                   // B*N*C
    float* out_adj  = out + (size_t)BB * NN * CC;            // B*N*N
    float* out_mask = out_adj + (size_t)BB * NN * NN;        // B*N
    float* out_nn   = out_mask + (size_t)BB * NN;            // B

    k_prep<<<33, 256>>>(W, bv, pool);
    k_t<<<(BB * NN) / 8, 256>>>(x);
    k_adjscan<<<(BB * NN) / 8, 256>>>(adj);
    k_rank<<<dim3(8, BB), 1024>>>(mask, nnod, out_mask);
    k_compact<<<BB, 1024>>>(nnod, out_nn);
    k_zero_dead<<<dim3(NN, BB), 64>>>(out_x);
    k_gather<<<dim3(NN / 4, BB), 256>>>(x);
    k_gemm<<<dim3(NN / GM, CC / GN, BB), 256>>>(W, bv, out_x);
    k_adjout<<<dim3(NN, BB), 256>>>(out_adj);
}

// round 6
// speedup vs baseline: 1.7733x; 1.1533x over previous
#include <cuda_runtime.h>
#include <cstdint>
#include <math.h>

#define BB 16
#define NN 1024
#define CC 256

// ---------------- scratch (__device__ globals: allocation-free) ----------------
__device__ float          g_Wp[CC];            // W @ pooling  (row dots)
__device__ float          g_scal[2];           // [0] = 1/||p||, [1] = b.p
__device__ float          g_t[BB * NN];        // x . Wp  per node
__device__ float          g_y[BB * NN];        // scores
__device__ float          g_mf[BB * NN];       // new mask (float)
__device__ int            g_cnt[BB * NN];      // nnz per adj row
__device__ unsigned short g_idx[(size_t)BB * NN * NN]; // nnz col indices per row
__device__ int            g_rows[BB * NN];     // compacted surviving node ids per batch
__device__ int            g_dead[BB * NN];     // compacted dead node ids per batch
__device__ int            g_nrows[BB];         // surviving count per batch
__device__ int            g_ndead[BB];         // dead count per batch
__device__ float          g_gc[(size_t)BB * NN * CC];  // gathered sums, compact (16 MB)

// ---------------- tf32 split helpers ----------------
__device__ __forceinline__ void tf32split(float v, float& hi, float& lo) {
    unsigned h;
    asm("cvt.rna.tf32.f32 %0, %1;" : "=r"(h) : "f"(v));
    hi = __uint_as_float(h);
    float l = v - hi;              // exact in fp32 (<=14 significant bits)
    unsigned h2;
    asm("cvt.rna.tf32.f32 %0, %1;" : "=r"(h2) : "f"(l));
    lo = __uint_as_float(h2);
}

#define MMA_TF32(d, a, b)                                                       \
    asm volatile(                                                               \
        "mma.sync.aligned.m16n8k8.row.col.f32.tf32.tf32.f32 "                   \
        "{%0,%1,%2,%3},{%4,%5,%6,%7},{%8,%9},{%0,%1,%2,%3};"                    \
        : "+f"((d)[0]), "+f"((d)[1]), "+f"((d)[2]), "+f"((d)[3])                \
        : "r"((a)[0]), "r"((a)[1]), "r"((a)[2]), "r"((a)[3]),                   \
          "r"((b)[0]), "r"((b)[1]))

// ---------------- K_prep: blocks 0..31: Wp rows; block 32: scal ----------------
__global__ void k_prep(const float* __restrict__ W,
                       const float* __restrict__ b,
                       const float* __restrict__ p) {
    int tid = threadIdx.x;  // 256
    if (blockIdx.x == 32) {
        __shared__ float s1[CC], s2[CC];
        float pc = p[tid];
        s1[tid] = pc * pc;
        s2[tid] = b[tid] * pc;
        __syncthreads();
        for (int off = CC / 2; off > 0; off >>= 1) {
            if (tid < off) { s1[tid] += s1[tid + off]; s2[tid] += s2[tid + off]; }
            __syncthreads();
        }
        if (tid == 0) {
            g_scal[0] = 1.0f / sqrtf(s1[0]);
            g_scal[1] = s2[0];
        }
        return;
    }
    __shared__ float ps[CC];
    ps[tid] = p[tid];
    __syncthreads();
    int warp = tid >> 5, lane = tid & 31;
    int r = blockIdx.x * 8 + warp;
    const float* wr = W + (size_t)r * CC;
    float acc = 0.f;
#pragma unroll
    for (int j = lane; j < CC; j += 32) acc += wr[j] * ps[j];
    for (int o = 16; o > 0; o >>= 1) acc += __shfl_down_sync(0xffffffffu, acc, o);
    if (lane == 0) g_Wp[r] = acc;
}

// ---------------- K_t: t[b,n] = x[b,n,:] . Wp  (warp per row, float4) ----------------
__global__ void k_t(const float* __restrict__ x) {
    __shared__ float4 wp4[CC / 4];
    int tid = threadIdx.x;  // 256
    if (tid < CC / 4) wp4[tid] = ((const float4*)g_Wp)[tid];
    __syncthreads();
    int warp = tid >> 5, lane = tid & 31;
    int row = blockIdx.x * 8 + warp;           // [0, BB*NN)
    const float4* xr = (const float4*)(x + (size_t)row * CC);
    float4 v0 = xr[lane];
    float4 v1 = xr[lane + 32];
    float4 w0 = wp4[lane];
    float4 w1 = wp4[lane + 32];
    float acc = v0.x * w0.x + v0.y * w0.y + v0.z * w0.z + v0.w * w0.w
              + v1.x * w1.x + v1.y * w1.y + v1.z * w1.z + v1.w * w1.w;
    for (int o = 16; o > 0; o >>= 1) acc += __shfl_down_sync(0xffffffffu, acc, o);
    if (lane == 0) g_t[row] = acc;
}

// ---------------- K_adjscan: one float4 pass over adj -> y scores + nnz lists ----------------
__global__ void k_adjscan(const float* __restrict__ adj) {
    __shared__ float s[NN];
    int tid = threadIdx.x;
    int b = blockIdx.x >> 7;           // 128 blocks per batch
    int chunk = blockIdx.x & 127;
    for (int i = tid; i < NN; i += blockDim.x) s[i] = g_t[b * NN + i];
    __syncthreads();
    int warp = tid >> 5, lane = tid & 31;
    int n = chunk * 8 + warp;
    const float* ar = adj + ((size_t)b * NN + n) * NN;
    unsigned short* ir = g_idx + ((size_t)b * NN + n) * NN;
    float acc = 0.f;
    int cnt = 0;
    for (int m0 = 0; m0 < NN; m0 += 128) {
        float4 v = *(const float4*)(ar + m0 + lane * 4);
        float4 sv = *(const float4*)(&s[m0 + lane * 4]);
        acc += v.x * sv.x + v.y * sv.y;
        acc += v.z * sv.z + v.w * sv.w;
        float vv[4] = {v.x, v.y, v.z, v.w};
#pragma unroll
        for (int u = 0; u < 4; u++) {
            unsigned ball = __ballot_sync(0xffffffffu, vv[u] != 0.0f);
            if (vv[u] != 0.0f) {
                int pos = cnt + __popc(ball & ((1u << lane) - 1u));
                ir[pos] = (unsigned short)(m0 + lane * 4 + u);
            }
            cnt += __popc(ball);
        }
    }
    for (int o = 16; o > 0; o >>= 1) acc += __shfl_down_sync(0xffffffffu, acc, o);
    if (lane == 0) {
        g_cnt[b * NN + n] = cnt;
        g_y[b * NN + n] = (acc + g_scal[1]) * g_scal[0];
    }
}

// ---------------- K_rank: pairwise stable ranking, conflict-free float4 LDS ----------------
__global__ void k_rank(const int* __restrict__ mask,
                       const int* __restrict__ n_nodes,
                       float* __restrict__ out_mask) {
    int b = blockIdx.y;
    __shared__ float ys[NN];
    int t = threadIdx.x;               // 1024
    int mt = mask[b * NN + t];
    float yv = g_y[b * NN + t];
    ys[t] = mt ? yv : __int_as_float(0x7f800000);  // +INF for unmasked
    __syncthreads();
    int i   = blockIdx.x * 128 + (t >> 3);
    int sub = t & 7;
    float yi = ys[i];
    const float4* ys4 = (const float4*)ys;
    int r = 0;
#pragma unroll 8
    for (int k = 0; k < 32; k++) {
        int f = sub + 8 * k;           // float4 chunk index
        float4 v = ys4[f];
        int j = f * 4;
        r += (v.x < yi || (v.x == yi && j     < i)) ? 1 : 0;
        r += (v.y < yi || (v.y == yi && j + 1 < i)) ? 1 : 0;
        r += (v.z < yi || (v.z == yi && j + 2 < i)) ? 1 : 0;
        r += (v.w < yi || (v.w == yi && j + 3 < i)) ? 1 : 0;
    }
    r += __shfl_down_sync(0xffffffffu, r, 4, 8);
    r += __shfl_down_sync(0xffffffffu, r, 2, 8);
    r += __shfl_down_sync(0xffffffffu, r, 1, 8);
    if (sub == 0) {
        int mi = mask[b * NN + i];
        int nrem = (int)((float)n_nodes[b] * 0.5f);   // (1 - POOL_RATIO)
        int nm = (mi != 0 && r >= nrem) ? 1 : 0;
        g_mf[b * NN + i] = (float)nm;
        out_mask[b * NN + i] = (float)nm;
    }
}

// ---------------- K_compact: warp-scan -> surviving + dead node lists ----------------
__global__ void k_compact(const int* __restrict__ n_nodes, float* __restrict__ out_nn) {
    int b = blockIdx.x;
    int i = threadIdx.x;               // 1024
    int lane = i & 31, w = i >> 5;
    int nm = (int)g_mf[b * NN + i];
    unsigned ball = __ballot_sync(0xffffffffu, nm != 0);
    int wpre = __popc(ball & ((1u << lane) - 1u));
    __shared__ int wsum[32];
    if (lane == 0) wsum[w] = __popc(ball);
    __syncthreads();
    if (w == 0) {
        int orig = wsum[lane];
        int v = orig;
        for (int o = 1; o < 32; o <<= 1) {
            int u = __shfl_up_sync(0xffffffffu, v, o);
            if (lane >= o) v += u;
        }
        wsum[lane] = v - orig;   // exclusive
    }
    __syncthreads();
    int excl = wsum[w] + wpre;
    if (nm) g_rows[b * NN + excl] = i;
    else    g_dead[b * NN + (i - excl)] = i;
    if (i == NN - 1) {
        int tot = excl + nm;
        g_nrows[b] = tot;
        g_ndead[b] = NN - tot;
        int nrem = (int)((float)n_nodes[b] * 0.5f);
        out_nn[b] = (float)(n_nodes[b] - nrem);
    }
}

// ---------------- K_gather: 4 rows per block, float4 channels, MLP-4 ----------------
__global__ __launch_bounds__(256) void k_gather(const float* __restrict__ x) {
    int b = blockIdx.y;
    int nrows = g_nrows[b];
    if (blockIdx.x * 4 >= nrows) return;
    int tid = threadIdx.x;
    int sub = tid >> 6;        // row within block
    int ct  = tid & 63;        // float4 channel group
    int pos = blockIdx.x * 4 + sub;
    bool active = pos < nrows;

    __shared__ unsigned short sidx[4][128];
    int cnt = 0;
    const unsigned short* ir = nullptr;
    if (active) {
        int row = g_rows[b * NN + pos];
        cnt = g_cnt[b * NN + row];
        ir  = g_idx + ((size_t)b * NN + row) * NN;
        int lim = cnt < 128 ? cnt : 128;
        for (int t = ct; t < lim; t += 64) sidx[sub][t] = ir[t];
    }
    __syncthreads();
    if (!active) return;

    const float* xb = x + (size_t)b * NN * CC + ct * 4;
    float4 a0 = make_float4(0.f, 0.f, 0.f, 0.f);
    float4 a1 = make_float4(0.f, 0.f, 0.f, 0.f);
    float4 a2 = make_float4(0.f, 0.f, 0.f, 0.f);
    float4 a3 = make_float4(0.f, 0.f, 0.f, 0.f);
    int t = 0;
    for (; t + 4 <= cnt && t + 4 <= 128; t += 4) {
        float4 v0 = *(const float4*)(xb + (int)sidx[sub][t] * CC);
        float4 v1 = *(const float4*)(xb + (int)sidx[sub][t + 1] * CC);
        float4 v2 = *(const float4*)(xb + (int)sidx[sub][t + 2] * CC);
        float4 v3 = *(const float4*)(xb + (int)sidx[sub][t + 3] * CC);
        a0.x += v0.x; a0.y += v0.y; a0.z += v0.z; a0.w += v0.w;
        a1.x += v1.x; a1.y += v1.y; a1.z += v1.z; a1.w += v1.w;
        a2.x += v2.x; a2.y += v2.y; a2.z += v2.z; a2.w += v2.w;
        a3.x += v3.x; a3.y += v3.y; a3.z += v3.z; a3.w += v3.w;
    }
    for (; t < cnt; t++) {
        int idx = (t < 128) ? (int)sidx[sub][t] : (int)ir[t];
        float4 v = *(const float4*)(xb + idx * CC);
        a0.x += v.x; a0.y += v.y; a0.z += v.z; a0.w += v.w;
    }
    float4 r;
    r.x = (a0.x + a1.x) + (a2.x + a3.x);
    r.y = (a0.y + a1.y) + (a2.y + a3.y);
    r.z = (a0.z + a1.z) + (a2.z + a3.z);
    r.w = (a0.w + a1.w) + (a2.w + a3.w);
    *(float4*)(g_gc + ((size_t)b * NN + pos) * CC + ct * 4) = r;
}

// ---------------- K_gemm: tf32 MMA, 3-term split, dead-row zeroing folded in ----------------
#define GM 128
#define GN 128
#define GK 16
#define AP 20    // A-tile k pitch (floats): gid*20 mod 32 spans 8 banks -> conflict-free
#define BPD 136  // B-tile n pitch

__global__ __launch_bounds__(256) void k_gemm(const float* __restrict__ W,
                                              const float* __restrict__ bvec,
                                              float* __restrict__ out_x) {
    __shared__ float Ah[GM][AP], Al[GM][AP];
    __shared__ float Bh[GK][BPD], Bl[GK][BPD];
    __shared__ float bs[GN];
    int b = blockIdx.z;
    int nrows = g_nrows[b];
    int row0 = blockIdx.x * GM;
    int col0 = blockIdx.y * GN;
    int tid = threadIdx.x;
    int lane = tid & 31, warp = tid >> 5;
    int wm = warp & 3, wn = warp >> 2;       // 4 M-warps x 2 N-warps
    int gid = lane >> 2, tig = lane & 3;

    if (tid < GN) bs[tid] = bvec[col0 + tid];

    float acc[2][8][4];
#pragma unroll
    for (int i = 0; i < 2; i++)
#pragma unroll
        for (int j = 0; j < 8; j++)
#pragma unroll
            for (int k = 0; k < 4; k++) acc[i][j][k] = 0.f;

    if (row0 < nrows) {
        int rows_in = nrows - row0; if (rows_in > GM) rows_in = GM;
        const float* A = g_gc + ((size_t)b * NN + row0) * CC;
        for (int kt = 0; kt < CC; kt += GK) {
            // ---- stage A,B with tf32 hi/lo split ----
#pragma unroll
            for (int u = 0; u < 2; u++) {
                int idx = tid + u * 256;
                int m = idx >> 2, k4 = idx & 3;
                float4 v = (m < rows_in)
                               ? *(const float4*)(A + (size_t)m * CC + kt + k4 * 4)
                               : make_float4(0.f, 0.f, 0.f, 0.f);
                float4 h4, l4;
                tf32split(v.x, h4.x, l4.x);
                tf32split(v.y, h4.y, l4.y);
                tf32split(v.z, h4.z, l4.z);
                tf32split(v.w, h4.w, l4.w);
                *(float4*)&Ah[m][k4 * 4] = h4;
                *(float4*)&Al[m][k4 * 4] = l4;
                int k = idx >> 5, c4 = idx & 31;
                float4 w = *(const float4*)(W + (size_t)(kt + k) * CC + col0 + c4 * 4);
                tf32split(w.x, h4.x, l4.x);
                tf32split(w.y, h4.y, l4.y);
                tf32split(w.z, h4.z, l4.z);
                tf32split(w.w, h4.w, l4.w);
                *(float4*)&Bh[k][c4 * 4] = h4;
                *(float4*)&Bl[k][c4 * 4] = l4;
            }
            __syncthreads();
            // ---- two k8 steps ----
#pragma unroll
            for (int k8 = 0; k8 < GK; k8 += 8) {
                unsigned ah[2][4], al[2][4], bh[8][2], bl[8][2];
#pragma unroll
                for (int mt = 0; mt < 2; mt++) {
                    int r = wm * 32 + mt * 16 + gid;
                    ah[mt][0] = __float_as_uint(Ah[r][k8 + tig]);
                    ah[mt][1] = __float_as_uint(Ah[r + 8][k8 + tig]);
                    ah[mt][2] = __float_as_uint(Ah[r][k8 + tig + 4]);
                    ah[mt][3] = __float_as_uint(Ah[r + 8][k8 + tig + 4]);
                    al[mt][0] = __float_as_uint(Al[r][k8 + tig]);
                    al[mt][1] = __float_as_uint(Al[r + 8][k8 + tig]);
                    al[mt][2] = __float_as_uint(Al[r][k8 + tig + 4]);
                    al[mt][3] = __float_as_uint(Al[r + 8][k8 + tig + 4]);
                }
#pragma unroll
                for (int nt = 0; nt < 8; nt++) {
                    int c = wn * 64 + nt * 8 + gid;
                    bh[nt][0] = __float_as_uint(Bh[k8 + tig][c]);
                    bh[nt][1] = __float_as_uint(Bh[k8 + tig + 4][c]);
                    bl[nt][0] = __float_as_uint(Bl[k8 + tig][c]);
                    bl[nt][1] = __float_as_uint(Bl[k8 + tig + 4][c]);
                }
#pragma unroll
                for (int mt = 0; mt < 2; mt++)
#pragma unroll
                    for (int nt = 0; nt < 8; nt++) {
                        MMA_TF32(acc[mt][nt], al[mt], bh[nt]);
                        MMA_TF32(acc[mt][nt], ah[mt], bl[nt]);
                        MMA_TF32(acc[mt][nt], ah[mt], bh[nt]);
                    }
            }
            __syncthreads();
        }
    }
    __syncthreads();   // bs visible for all paths (uniform)

    // ---- epilogue: live rows -> (acc+b)*tanh(y); dead rows -> zeros ----
#pragma unroll
    for (int mt = 0; mt < 2; mt++)
#pragma unroll
        for (int rh = 0; rh < 2; rh++) {
            int g = row0 + wm * 32 + mt * 16 + rh * 8 + gid;
            bool live = g < nrows;
            int node = live ? g_rows[b * NN + g] : g_dead[b * NN + g - nrows];
            float tval = live ? tanhf(g_y[b * NN + node]) : 0.f;
            float* orow = out_x + ((size_t)b * NN + node) * CC + col0 + wn * 64 + 2 * tig;
#pragma unroll
            for (int nt = 0; nt < 8; nt++) {
                float2 o;
                if (live) {
                    int c = wn * 64 + nt * 8 + 2 * tig;
                    o.x = (acc[mt][nt][rh * 2]     + bs[c])     * tval;
                    o.y = (acc[mt][nt][rh * 2 + 1] + bs[c + 1]) * tval;
                } else {
                    o.x = 0.f; o.y = 0.f;
                }
                *(float2*)(orow + nt * 8) = o;
            }
        }
}

// ---------------- K_adjout: dense adj_out rows (zeros or expanded nnz) ----------------
__global__ __launch_bounds__(256) void k_adjout(float* __restrict__ out_adj) {
    int b = blockIdx.y;
    int n = blockIdx.x;
    int tid = threadIdx.x;  // 256
    float4* orow = (float4*)(out_adj + ((size_t)b * NN + n) * NN);
    if (g_mf[b * NN + n] == 0.0f) {
        orow[tid] = make_float4(0.f, 0.f, 0.f, 0.f);    // 256 x 16B = 4KB
        return;
    }
    __shared__ float srow[NN];
    *(float4*)&srow[tid * 4] = make_float4(0.f, 0.f, 0.f, 0.f);
    __syncthreads();
    int cnt = g_cnt[b * NN + n];
    const unsigned short* ir = g_idx + ((size_t)b * NN + n) * NN;
    for (int t = tid; t < cnt; t += 256) {
        int m = ir[t];
        if (g_mf[b * NN + m] != 0.0f) srow[m] = 1.0f;
    }
    __syncthreads();
    orow[tid] = *(float4*)&srow[tid * 4];
}

// ---------------- launch ----------------
extern "C" void kernel_launch(void* const* d_in, const int* in_sizes, int n_in,
                              void* d_out, int out_size) {
    const float* x    = (const float*)d_in[0];  // [B,N,C]
    const float* adj  = (const float*)d_in[1];  // [B,N,N]
    const int*   mask = (const int*)d_in[2];    // [B,N]
    const int*   nnod = (const int*)d_in[3];    // [B]
    const float* W    = (const float*)d_in[4];  // [C,C]
    const float* bv   = (const float*)d_in[5];  // [C]
    const float* pool = (const float*)d_in[6];  // [C,1]

    float* out = (float*)d_out;
    float* out_x    = out;                                   // B*N*C
    float* out_adj  = out + (size_t)BB * NN * CC;            // B*N*N
    float* out_mask = out_adj + (size_t)BB * NN * NN;        // B*N
    float* out_nn   = out_mask + (size_t)BB * NN;            // B

    k_prep<<<33, 256>>>(W, bv, pool);
    k_t<<<(BB * NN) / 8, 256>>>(x);
    k_adjscan<<<(BB * NN) / 8, 256>>>(adj);
    k_rank<<<dim3(8, BB), 1024>>>(mask, nnod, out_mask);
    k_compact<<<BB, 1024>>>(nnod, out_nn);
    k_gather<<<dim3(NN / 4, BB), 256>>>(x);
    k_gemm<<<dim3(NN / GM, CC / GN, BB), 256>>>(W, bv, out_x);
    k_adjout<<<dim3(NN, BB), 256>>>(out_adj);
}

// round 7
// speedup vs baseline: 1.8093x; 1.0203x over previous
#include <cuda_runtime.h>
#include <cstdint>
#include <math.h>

#define BB 16
#define NN 1024
#define CC 256

// ---------------- scratch (__device__ globals: allocation-free) ----------------
__device__ float          g_Wp[CC];            // W @ pooling  (row dots)
__device__ float          g_scal[2];           // [0] = 1/||p||, [1] = b.p
__device__ float          g_t[BB * NN];        // x . Wp  per node
__device__ float          g_y[BB * NN];        // scores
__device__ float          g_mf[BB * NN];       // new mask (float)
__device__ int            g_cnt[BB * NN];      // nnz per adj row
__device__ unsigned short g_idx[(size_t)BB * NN * NN]; // nnz col indices per row
__device__ int            g_rows[BB * NN];     // packed (node | cnt<<12) live rows
__device__ int            g_dead[BB * NN];     // compacted dead node ids per batch
__device__ int            g_nrows[BB];         // surviving count per batch
__device__ int            g_ndead[BB];         // dead count per batch
__device__ float          g_gc[(size_t)BB * NN * CC];  // gathered sums, compact (16 MB)

// ---------------- tf32 split helpers ----------------
__device__ __forceinline__ void tf32split(float v, float& hi, float& lo) {
    unsigned h;
    asm("cvt.rna.tf32.f32 %0, %1;" : "=r"(h) : "f"(v));
    hi = __uint_as_float(h);
    float l = v - hi;              // exact in fp32 (<=14 significant bits)
    unsigned h2;
    asm("cvt.rna.tf32.f32 %0, %1;" : "=r"(h2) : "f"(l));
    lo = __uint_as_float(h2);
}

#define MMA_TF32(d, a, b)                                                       \
    asm volatile(                                                               \
        "mma.sync.aligned.m16n8k8.row.col.f32.tf32.tf32.f32 "                   \
        "{%0,%1,%2,%3},{%4,%5,%6,%7},{%8,%9},{%0,%1,%2,%3};"                    \
        : "+f"((d)[0]), "+f"((d)[1]), "+f"((d)[2]), "+f"((d)[3])                \
        : "r"((a)[0]), "r"((a)[1]), "r"((a)[2]), "r"((a)[3]),                   \
          "r"((b)[0]), "r"((b)[1]))

// ---------------- K_prep: blocks 0..31: Wp rows; block 32: scal ----------------
__global__ void k_prep(const float* __restrict__ W,
                       const float* __restrict__ b,
                       const float* __restrict__ p) {
    int tid = threadIdx.x;  // 256
    if (blockIdx.x == 32) {
        __shared__ float s1[CC], s2[CC];
        float pc = p[tid];
        s1[tid] = pc * pc;
        s2[tid] = b[tid] * pc;
        __syncthreads();
        for (int off = CC / 2; off > 0; off >>= 1) {
            if (tid < off) { s1[tid] += s1[tid + off]; s2[tid] += s2[tid + off]; }
            __syncthreads();
        }
        if (tid == 0) {
            g_scal[0] = 1.0f / sqrtf(s1[0]);
            g_scal[1] = s2[0];
        }
        return;
    }
    __shared__ float ps[CC];
    ps[tid] = p[tid];
    __syncthreads();
    int warp = tid >> 5, lane = tid & 31;
    int r = blockIdx.x * 8 + warp;
    const float* wr = W + (size_t)r * CC;
    float acc = 0.f;
#pragma unroll
    for (int j = lane; j < CC; j += 32) acc += wr[j] * ps[j];
    for (int o = 16; o > 0; o >>= 1) acc += __shfl_down_sync(0xffffffffu, acc, o);
    if (lane == 0) g_Wp[r] = acc;
}

// ---------------- K_t: t[b,n] = x[b,n,:] . Wp  (warp per row, float4) ----------------
__global__ void k_t(const float* __restrict__ x) {
    __shared__ float4 wp4[CC / 4];
    int tid = threadIdx.x;  // 256
    if (tid < CC / 4) wp4[tid] = ((const float4*)g_Wp)[tid];
    __syncthreads();
    int warp = tid >> 5, lane = tid & 31;
    int row = blockIdx.x * 8 + warp;           // [0, BB*NN)
    const float4* xr = (const float4*)(x + (size_t)row * CC);
    float4 v0 = xr[lane];
    float4 v1 = xr[lane + 32];
    float4 w0 = wp4[lane];
    float4 w1 = wp4[lane + 32];
    float acc = v0.x * w0.x + v0.y * w0.y + v0.z * w0.z + v0.w * w0.w
              + v1.x * w1.x + v1.y * w1.y + v1.z * w1.z + v1.w * w1.w;
    for (int o = 16; o > 0; o >>= 1) acc += __shfl_down_sync(0xffffffffu, acc, o);
    if (lane == 0) g_t[row] = acc;
}

// ---------------- K_adjscan: one float4 pass over adj -> y scores + nnz lists ----------------
__global__ void k_adjscan(const float* __restrict__ adj) {
    __shared__ float s[NN];
    int tid = threadIdx.x;
    int b = blockIdx.x >> 7;           // 128 blocks per batch
    int chunk = blockIdx.x & 127;
    for (int i = tid; i < NN; i += blockDim.x) s[i] = g_t[b * NN + i];
    __syncthreads();
    int warp = tid >> 5, lane = tid & 31;
    int n = chunk * 8 + warp;
    const float* ar = adj + ((size_t)b * NN + n) * NN;
    unsigned short* ir = g_idx + ((size_t)b * NN + n) * NN;
    float acc = 0.f;
    int cnt = 0;
    for (int m0 = 0; m0 < NN; m0 += 128) {
        float4 v = *(const float4*)(ar + m0 + lane * 4);
        float4 sv = *(const float4*)(&s[m0 + lane * 4]);
        acc += v.x * sv.x + v.y * sv.y;
        acc += v.z * sv.z + v.w * sv.w;
        float vv[4] = {v.x, v.y, v.z, v.w};
#pragma unroll
        for (int u = 0; u < 4; u++) {
            unsigned ball = __ballot_sync(0xffffffffu, vv[u] != 0.0f);
            if (vv[u] != 0.0f) {
                int pos = cnt + __popc(ball & ((1u << lane) - 1u));
                ir[pos] = (unsigned short)(m0 + lane * 4 + u);
            }
            cnt += __popc(ball);
        }
    }
    for (int o = 16; o > 0; o >>= 1) acc += __shfl_down_sync(0xffffffffu, acc, o);
    if (lane == 0) {
        g_cnt[b * NN + n] = cnt;
        g_y[b * NN + n] = (acc + g_scal[1]) * g_scal[0];
    }
}

// ---------------- K_rank: u64 sortable keys, one ISETP.64 per element ----------------
// key = monotone(y) << 10 | index for masked nodes (unique, stable-order-preserving);
// unmasked -> UINT64_MAX (never counted by strict <).
__global__ void k_rank(const int* __restrict__ mask,
                       const int* __restrict__ n_nodes,
                       float* __restrict__ out_mask) {
    int b = blockIdx.y;
    __shared__ unsigned long long ks[NN];
    int t = threadIdx.x;               // 1024
    int mt = mask[b * NN + t];
    float yv = g_y[b * NN + t];
    unsigned u = __float_as_uint(yv);
    u = (u & 0x80000000u) ? ~u : (u | 0x80000000u);  // monotone float->uint
    ks[t] = mt ? ((((unsigned long long)u) << 10) | (unsigned)t)
               : 0xFFFFFFFFFFFFFFFFull;
    __syncthreads();
    int i   = blockIdx.x * 128 + (t >> 3);
    int sub = t & 7;
    unsigned long long ki = ks[i];     // broadcast within 8-thread group
    const ulonglong2* ks2 = (const ulonglong2*)ks;
    int r = 0;
#pragma unroll 8
    for (int k = 0; k < 64; k++) {
        ulonglong2 v = ks2[sub + 8 * k];   // 8 distinct 16B addrs/warp: conflict-free
        r += (v.x < ki) ? 1 : 0;
        r += (v.y < ki) ? 1 : 0;
    }
    r += __shfl_down_sync(0xffffffffu, r, 4, 8);
    r += __shfl_down_sync(0xffffffffu, r, 2, 8);
    r += __shfl_down_sync(0xffffffffu, r, 1, 8);
    if (sub == 0) {
        int mi = mask[b * NN + i];
        int nrem = (int)((float)n_nodes[b] * 0.5f);   // (1 - POOL_RATIO)
        int nm = (mi != 0 && r >= nrem) ? 1 : 0;
        g_mf[b * NN + i] = (float)nm;
        out_mask[b * NN + i] = (float)nm;
    }
}

// ---------------- K_compact: warp-scan -> packed live list + dead list ----------------
__global__ void k_compact(const int* __restrict__ n_nodes, float* __restrict__ out_nn) {
    int b = blockIdx.x;
    int i = threadIdx.x;               // 1024
    int lane = i & 31, w = i >> 5;
    int nm = (int)g_mf[b * NN + i];
    unsigned ball = __ballot_sync(0xffffffffu, nm != 0);
    int wpre = __popc(ball & ((1u << lane) - 1u));
    __shared__ int wsum[32];
    if (lane == 0) wsum[w] = __popc(ball);
    __syncthreads();
    if (w == 0) {
        int orig = wsum[lane];
        int v = orig;
        for (int o = 1; o < 32; o <<= 1) {
            int u = __shfl_up_sync(0xffffffffu, v, o);
            if (lane >= o) v += u;
        }
        wsum[lane] = v - orig;   // exclusive
    }
    __syncthreads();
    int excl = wsum[w] + wpre;
    if (nm) g_rows[b * NN + excl] = i | (g_cnt[b * NN + i] << 12);  // pack cnt
    else    g_dead[b * NN + (i - excl)] = i;
    if (i == NN - 1) {
        int tot = excl + nm;
        g_nrows[b] = tot;
        g_ndead[b] = NN - tot;
        int nrem = (int)((float)n_nodes[b] * 0.5f);
        out_nn[b] = (float)(n_nodes[b] - nrem);
    }
}

// ---------------- K_gather: 4 rows per block, float4 channels, MLP-4 ----------------
__global__ __launch_bounds__(256) void k_gather(const float* __restrict__ x) {
    int b = blockIdx.y;
    int nrows = g_nrows[b];
    if (blockIdx.x * 4 >= nrows) return;
    int tid = threadIdx.x;
    int sub = tid >> 6;        // row within block
    int ct  = tid & 63;        // float4 channel group
    int pos = blockIdx.x * 4 + sub;
    bool active = pos < nrows;

    __shared__ unsigned short sidx[4][128];
    int cnt = 0;
    const unsigned short* ir = nullptr;
    if (active) {
        int v = g_rows[b * NN + pos];
        int row = v & 1023;
        cnt = v >> 12;
        ir  = g_idx + ((size_t)b * NN + row) * NN;
        int lim = cnt < 128 ? cnt : 128;
        for (int t = ct; t < lim; t += 64) sidx[sub][t] = ir[t];
    }
    __syncthreads();
    if (!active) return;

    const float* xb = x + (size_t)b * NN * CC + ct * 4;
    float4 a0 = make_float4(0.f, 0.f, 0.f, 0.f);
    float4 a1 = make_float4(0.f, 0.f, 0.f, 0.f);
    float4 a2 = make_float4(0.f, 0.f, 0.f, 0.f);
    float4 a3 = make_float4(0.f, 0.f, 0.f, 0.f);
    int t = 0;
    for (; t + 4 <= cnt && t + 4 <= 128; t += 4) {
        float4 v0 = *(const float4*)(xb + (int)sidx[sub][t] * CC);
        float4 v1 = *(const float4*)(xb + (int)sidx[sub][t + 1] * CC);
        float4 v2 = *(const float4*)(xb + (int)sidx[sub][t + 2] * CC);
        float4 v3 = *(const float4*)(xb + (int)sidx[sub][t + 3] * CC);
        a0.x += v0.x; a0.y += v0.y; a0.z += v0.z; a0.w += v0.w;
        a1.x += v1.x; a1.y += v1.y; a1.z += v1.z; a1.w += v1.w;
        a2.x += v2.x; a2.y += v2.y; a2.z += v2.z; a2.w += v2.w;
        a3.x += v3.x; a3.y += v3.y; a3.z += v3.z; a3.w += v3.w;
    }
    for (; t < cnt; t++) {
        int idx = (t < 128) ? (int)sidx[sub][t] : (int)ir[t];
        float4 v = *(const float4*)(xb + idx * CC);
        a0.x += v.x; a0.y += v.y; a0.z += v.z; a0.w += v.w;
    }
    float4 r;
    r.x = (a0.x + a1.x) + (a2.x + a3.x);
    r.y = (a0.y + a1.y) + (a2.y + a3.y);
    r.z = (a0.z + a1.z) + (a2.z + a3.z);
    r.w = (a0.w + a1.w) + (a2.w + a3.w);
    *(float4*)(g_gc + ((size_t)b * NN + pos) * CC + ct * 4) = r;
}

// ---------------- K_gemm: tf32 MMA, 3-term split, dead-row zeroing folded in ----------------
#define GM 128
#define GN 128
#define GK 16
#define AP 20    // A-tile k pitch (floats): conflict-free fragment loads
#define BPD 136  // B-tile n pitch

__global__ __launch_bounds__(256) void k_gemm(const float* __restrict__ W,
                                              const float* __restrict__ bvec,
                                              float* __restrict__ out_x) {
    __shared__ float Ah[GM][AP], Al[GM][AP];
    __shared__ float Bh[GK][BPD], Bl[GK][BPD];
    __shared__ float bs[GN];
    int b = blockIdx.z;
    int nrows = g_nrows[b];
    int row0 = blockIdx.x * GM;
    int col0 = blockIdx.y * GN;
    int tid = threadIdx.x;
    int lane = tid & 31, warp = tid >> 5;
    int wm = warp & 3, wn = warp >> 2;       // 4 M-warps x 2 N-warps
    int gid = lane >> 2, tig = lane & 3;

    if (tid < GN) bs[tid] = bvec[col0 + tid];

    float acc[2][8][4];
#pragma unroll
    for (int i = 0; i < 2; i++)
#pragma unroll
        for (int j = 0; j < 8; j++)
#pragma unroll
            for (int k = 0; k < 4; k++) acc[i][j][k] = 0.f;

    if (row0 < nrows) {
        int rows_in = nrows - row0; if (rows_in > GM) rows_in = GM;
        const float* A = g_gc + ((size_t)b * NN + row0) * CC;
        for (int kt = 0; kt < CC; kt += GK) {
            // ---- stage A,B with tf32 hi/lo split ----
#pragma unroll
            for (int u = 0; u < 2; u++) {
                int idx = tid + u * 256;
                int m = idx >> 2, k4 = idx & 3;
                float4 v = (m < rows_in)
                               ? *(const float4*)(A + (size_t)m * CC + kt + k4 * 4)
                               : make_float4(0.f, 0.f, 0.f, 0.f);
                float4 h4, l4;
                tf32split(v.x, h4.x, l4.x);
                tf32split(v.y, h4.y, l4.y);
                tf32split(v.z, h4.z, l4.z);
                tf32split(v.w, h4.w, l4.w);
                *(float4*)&Ah[m][k4 * 4] = h4;
                *(float4*)&Al[m][k4 * 4] = l4;
                int k = idx >> 5, c4 = idx & 31;
                float4 w = *(const float4*)(W + (size_t)(kt + k) * CC + col0 + c4 * 4);
                tf32split(w.x, h4.x, l4.x);
                tf32split(w.y, h4.y, l4.y);
                tf32split(w.z, h4.z, l4.z);
                tf32split(w.w, h4.w, l4.w);
                *(float4*)&Bh[k][c4 * 4] = h4;
                *(float4*)&Bl[k][c4 * 4] = l4;
            }
            __syncthreads();
            // ---- two k8 steps ----
#pragma unroll
            for (int k8 = 0; k8 < GK; k8 += 8) {
                unsigned ah[2][4], al[2][4], bh[8][2], bl[8][2];
#pragma unroll
                for (int mt = 0; mt < 2; mt++) {
                    int r = wm * 32 + mt * 16 + gid;
                    ah[mt][0] = __float_as_uint(Ah[r][k8 + tig]);
                    ah[mt][1] = __float_as_uint(Ah[r + 8][k8 + tig]);
                    ah[mt][2] = __float_as_uint(Ah[r][k8 + tig + 4]);
                    ah[mt][3] = __float_as_uint(Ah[r + 8][k8 + tig + 4]);
                    al[mt][0] = __float_as_uint(Al[r][k8 + tig]);
                    al[mt][1] = __float_as_uint(Al[r + 8][k8 + tig]);
                    al[mt][2] = __float_as_uint(Al[r][k8 + tig + 4]);
                    al[mt][3] = __float_as_uint(Al[r + 8][k8 + tig + 4]);
                }
#pragma unroll
                for (int nt = 0; nt < 8; nt++) {
                    int c = wn * 64 + nt * 8 + gid;
                    bh[nt][0] = __float_as_uint(Bh[k8 + tig][c]);
                    bh[nt][1] = __float_as_uint(Bh[k8 + tig + 4][c]);
                    bl[nt][0] = __float_as_uint(Bl[k8 + tig][c]);
                    bl[nt][1] = __float_as_uint(Bl[k8 + tig + 4][c]);
                }
#pragma unroll
                for (int mt = 0; mt < 2; mt++)
#pragma unroll
                    for (int nt = 0; nt < 8; nt++) {
                        MMA_TF32(acc[mt][nt], al[mt], bh[nt]);
                        MMA_TF32(acc[mt][nt], ah[mt], bl[nt]);
                        MMA_TF32(acc[mt][nt], ah[mt], bh[nt]);
                    }
            }
            __syncthreads();
        }
    }
    __syncthreads();   // bs visible for all paths (uniform)

    // ---- epilogue: live rows -> (acc+b)*tanh(y); dead rows -> zeros ----
#pragma unroll
    for (int mt = 0; mt < 2; mt++)
#pragma unroll
        for (int rh = 0; rh < 2; rh++) {
            int g = row0 + wm * 32 + mt * 16 + rh * 8 + gid;
            bool live = g < nrows;
            int node = live ? (g_rows[b * NN + g] & 1023) : g_dead[b * NN + g - nrows];
            float tval = live ? tanhf(g_y[b * NN + node]) : 0.f;
            float* orow = out_x + ((size_t)b * NN + node) * CC + col0 + wn * 64 + 2 * tig;
#pragma unroll
            for (int nt = 0; nt < 8; nt++) {
                float2 o;
                if (live) {
                    int c = wn * 64 + nt * 8 + 2 * tig;
                    o.x = (acc[mt][nt][rh * 2]     + bs[c])     * tval;
                    o.y = (acc[mt][nt][rh * 2 + 1] + bs[c + 1]) * tval;
                } else {
                    o.x = 0.f; o.y = 0.f;
                }
                *(float2*)(orow + nt * 8) = o;
            }
        }
}

// ---------------- K_adjout: 4 dense rows per block, batch mask staged in smem ----------------
__global__ __launch_bounds__(256) void k_adjout(float* __restrict__ out_adj) {
    int b = blockIdx.y;
    int r0 = blockIdx.x * 4;
    int tid = threadIdx.x;   // 256
    int sub = tid >> 6, ct = tid & 63;
    __shared__ float smf[NN];
    __shared__ float srow[4 * NN];
    *(float4*)&smf[tid * 4] = *(const float4*)(g_mf + b * NN + tid * 4);
    float4 z = make_float4(0.f, 0.f, 0.f, 0.f);
#pragma unroll
    for (int u = 0; u < 4; u++)
        ((float4*)srow)[tid + u * 256] = z;
    __syncthreads();
    int n = r0 + sub;
    if (smf[n] != 0.f) {
        int cnt = g_cnt[b * NN + n];
        const unsigned short* ir = g_idx + ((size_t)b * NN + n) * NN;
        for (int t = ct; t < cnt; t += 64) {
            int m = ir[t];
            if (smf[m] != 0.f) srow[sub * NN + m] = 1.f;
        }
    }
    __syncthreads();
    float4* orow = (float4*)(out_adj + ((size_t)b * NN + n) * NN);
#pragma unroll
    for (int u = 0; u < 4; u++)
        orow[ct + u * 64] = *(float4*)&srow[sub * NN + (ct + u * 64) * 4];
}

// ---------------- launch ----------------
extern "C" void kernel_launch(void* const* d_in, const int* in_sizes, int n_in,
                              void* d_out, int out_size) {
    const float* x    = (const float*)d_in[0];  // [B,N,C]
    const float* adj  = (const float*)d_in[1];  // [B,N,N]
    const int*   mask = (const int*)d_in[2];    // [B,N]
    const int*   nnod = (const int*)d_in[3];    // [B]
    const float* W    = (const float*)d_in[4];  // [C,C]
    const float* bv   = (const float*)d_in[5];  // [C]
    const float* pool = (const float*)d_in[6];  // [C,1]

    float* out = (float*)d_out;
    float* out_x    = out;                                   // B*N*C
    float* out_adj  = out + (size_t)BB * NN * CC;            // B*N*N
    float* out_mask = out_adj + (size_t)BB * NN * NN;        // B*N
    float* out_nn   = out_mask + (size_t)BB * NN;            // B

    k_prep<<<33, 256>>>(W, bv, pool);
    k_t<<<(BB * NN) / 8, 256>>>(x);
    k_adjscan<<<(BB * NN) / 8, 256>>>(adj);
    k_rank<<<dim3(8, BB), 1024>>>(mask, nnod, out_mask);
    k_compact<<<BB, 1024>>>(nnod, out_nn);
    k_gather<<<dim3(NN / 4, BB), 256>>>(x);
    k_gemm<<<dim3(NN / GM, CC / GN, BB), 256>>>(W, bv, out_x);
    k_adjout<<<dim3(NN / 4, BB), 256>>>(out_adj);
}

// round 9
// speedup vs baseline: 1.9352x; 1.0695x over previous
#include <cuda_runtime.h>
#include <cstdint>
#include <math.h>

#define BB 16
#define NN 1024
#define CC 256

// ---------------- scratch (__device__ globals: allocation-free) ----------------
__device__ float    g_Wp[CC];             // W @ pooling  (row dots)
__device__ float    g_scal[2];            // [0] = 1/||p||, [1] = b.p
__device__ float    g_t[BB * NN];         // x . Wp  per node
__device__ float    g_y[BB * NN];         // scores
__device__ float    g_mf[BB * NN];        // new mask (float)
__device__ unsigned g_bits[(size_t)BB * NN * 32];  // adjacency bitmaps (2 MB)
__device__ int      g_rows[BB * NN];      // compacted surviving node ids per batch
__device__ int      g_dead[BB * NN];      // compacted dead node ids per batch
__device__ int      g_nrows[BB];          // surviving count per batch
__device__ int      g_ndead[BB];          // dead count per batch
__device__ float    g_gc[(size_t)BB * NN * CC];    // gathered sums, compact (16 MB)

// ---------------- tf32 split helpers ----------------
__device__ __forceinline__ void tf32split(float v, float& hi, float& lo) {
    unsigned h;
    asm("cvt.rna.tf32.f32 %0, %1;" : "=r"(h) : "f"(v));
    hi = __uint_as_float(h);
    float l = v - hi;              // exact in fp32 (<=14 significant bits)
    unsigned h2;
    asm("cvt.rna.tf32.f32 %0, %1;" : "=r"(h2) : "f"(l));
    lo = __uint_as_float(h2);
}

#define MMA_TF32(d, a, b)                                                       \
    asm volatile(                                                               \
        "mma.sync.aligned.m16n8k8.row.col.f32.tf32.tf32.f32 "                   \
        "{%0,%1,%2,%3},{%4,%5,%6,%7},{%8,%9},{%0,%1,%2,%3};"                    \
        : "+f"((d)[0]), "+f"((d)[1]), "+f"((d)[2]), "+f"((d)[3])                \
        : "r"((a)[0]), "r"((a)[1]), "r"((a)[2]), "r"((a)[3]),                   \
          "r"((b)[0]), "r"((b)[1]))

// ---------------- K_prep: blocks 0..31: Wp rows; block 32: scal ----------------
__global__ void k_prep(const float* __restrict__ W,
                       const float* __restrict__ b,
                       const float* __restrict__ p) {
    int tid = threadIdx.x;  // 256
    if (blockIdx.x == 32) {
        __shared__ float s1[CC], s2[CC];
        float pc = p[tid];
        s1[tid] = pc * pc;
        s2[tid] = b[tid] * pc;
        __syncthreads();
        for (int off = CC / 2; off > 0; off >>= 1) {
            if (tid < off) { s1[tid] += s1[tid + off]; s2[tid] += s2[tid + off]; }
            __syncthreads();
        }
        if (tid == 0) {
            g_scal[0] = 1.0f / sqrtf(s1[0]);
            g_scal[1] = s2[0];
        }
        return;
    }
    __shared__ float ps[CC];
    ps[tid] = p[tid];
    __syncthreads();
    int warp = tid >> 5, lane = tid & 31;
    int r = blockIdx.x * 8 + warp;
    const float* wr = W + (size_t)r * CC;
    float acc = 0.f;
#pragma unroll
    for (int j = lane; j < CC; j += 32) acc += wr[j] * ps[j];
    for (int o = 16; o > 0; o >>= 1) acc += __shfl_down_sync(0xffffffffu, acc, o);
    if (lane == 0) g_Wp[r] = acc;
}

// ---------------- K_t: t[b,n] = x[b,n,:] . Wp  (warp per row, float4) ----------------
__global__ void k_t(const float* __restrict__ x) {
    __shared__ float4 wp4[CC / 4];
    int tid = threadIdx.x;  // 256
    if (tid < CC / 4) wp4[tid] = ((const float4*)g_Wp)[tid];
    __syncthreads();
    int warp = tid >> 5, lane = tid & 31;
    int row = blockIdx.x * 8 + warp;           // [0, BB*NN)
    const float4* xr = (const float4*)(x + (size_t)row * CC);
    float4 v0 = xr[lane];
    float4 v1 = xr[lane + 32];
    float4 w0 = wp4[lane];
    float4 w1 = wp4[lane + 32];
    float acc = v0.x * w0.x + v0.y * w0.y + v0.z * w0.z + v0.w * w0.w
              + v1.x * w1.x + v1.y * w1.y + v1.z * w1.z + v1.w * w1.w;
    for (int o = 16; o > 0; o >>= 1) acc += __shfl_down_sync(0xffffffffu, acc, o);
    if (lane == 0) g_t[row] = acc;
}

// ---------------- K_adjscan: float4 pass over adj -> y scores + row BITMAPS ----------------
// Bit layout: column = chunk*128 + 4*bitpos + u  for word u (0..3) of chunk (0..7).
__global__ void k_adjscan(const float* __restrict__ adj) {
    __shared__ float s[NN];
    int tid = threadIdx.x;
    int b = blockIdx.x >> 7;           // 128 blocks per batch
    int chunk = blockIdx.x & 127;
    for (int i = tid; i < NN; i += blockDim.x) s[i] = g_t[b * NN + i];
    __syncthreads();
    int warp = tid >> 5, lane = tid & 31;
    int n = chunk * 8 + warp;
    const float* ar = adj + ((size_t)b * NN + n) * NN;
    uint4* br = (uint4*)(g_bits + ((size_t)(b * NN) + n) * 32);
    float acc = 0.f;
    for (int m0 = 0, c = 0; m0 < NN; m0 += 128, c++) {
        float4 v = *(const float4*)(ar + m0 + lane * 4);
        float4 sv = *(const float4*)(&s[m0 + lane * 4]);
        acc += v.x * sv.x + v.y * sv.y;
        acc += v.z * sv.z + v.w * sv.w;
        unsigned b0 = __ballot_sync(0xffffffffu, v.x != 0.0f);
        unsigned b1 = __ballot_sync(0xffffffffu, v.y != 0.0f);
        unsigned b2 = __ballot_sync(0xffffffffu, v.z != 0.0f);
        unsigned b3 = __ballot_sync(0xffffffffu, v.w != 0.0f);
        if (lane == 0) br[c] = make_uint4(b0, b1, b2, b3);
    }
    for (int o = 16; o > 0; o >>= 1) acc += __shfl_down_sync(0xffffffffu, acc, o);
    if (lane == 0) g_y[b * NN + n] = (acc + g_scal[1]) * g_scal[0];
}

// ---------------- K_rank: u64 sortable keys, one compare per element ----------------
__global__ void k_rank(const int* __restrict__ mask,
                       const int* __restrict__ n_nodes,
                       float* __restrict__ out_mask) {
    int b = blockIdx.y;
    __shared__ unsigned long long ks[NN];
    int t = threadIdx.x;               // 1024
    int mt = mask[b * NN + t];
    float yv = g_y[b * NN + t];
    unsigned u = __float_as_uint(yv);
    u = (u & 0x80000000u) ? ~u : (u | 0x80000000u);  // monotone float->uint
    ks[t] = mt ? ((((unsigned long long)u) << 10) | (unsigned)t)
               : 0xFFFFFFFFFFFFFFFFull;
    __syncthreads();
    int i   = blockIdx.x * 128 + (t >> 3);
    int sub = t & 7;
    unsigned long long ki = ks[i];
    const ulonglong2* ks2 = (const ulonglong2*)ks;
    int r = 0;
#pragma unroll 8
    for (int k = 0; k < 64; k++) {
        ulonglong2 v = ks2[sub + 8 * k];   // 8 distinct 16B addrs/warp: conflict-free
        r += (v.x < ki) ? 1 : 0;
        r += (v.y < ki) ? 1 : 0;
    }
    r += __shfl_down_sync(0xffffffffu, r, 4, 8);
    r += __shfl_down_sync(0xffffffffu, r, 2, 8);
    r += __shfl_down_sync(0xffffffffu, r, 1, 8);
    if (sub == 0) {
        int mi = mask[b * NN + i];
        int nrem = (int)((float)n_nodes[b] * 0.5f);   // (1 - POOL_RATIO)
        int nm = (mi != 0 && r >= nrem) ? 1 : 0;
        g_mf[b * NN + i] = (float)nm;
        out_mask[b * NN + i] = (float)nm;
    }
}

// ---------------- K_compact: warp-scan -> live list + dead list ----------------
__global__ void k_compact(const int* __restrict__ n_nodes, float* __restrict__ out_nn) {
    int b = blockIdx.x;
    int i = threadIdx.x;               // 1024
    int lane = i & 31, w = i >> 5;
    int nm = (int)g_mf[b * NN + i];
    unsigned ball = __ballot_sync(0xffffffffu, nm != 0);
    int wpre = __popc(ball & ((1u << lane) - 1u));
    __shared__ int wsum[32];
    if (lane == 0) wsum[w] = __popc(ball);
    __syncthreads();
    if (w == 0) {
        int orig = wsum[lane];
        int v = orig;
        for (int o = 1; o < 32; o <<= 1) {
            int u = __shfl_up_sync(0xffffffffu, v, o);
            if (lane >= o) v += u;
        }
        wsum[lane] = v - orig;   // exclusive
    }
    __syncthreads();
    int excl = wsum[w] + wpre;
    if (nm) g_rows[b * NN + excl] = i;
    else    g_dead[b * NN + (i - excl)] = i;
    if (i == NN - 1) {
        int tot = excl + nm;
        g_nrows[b] = tot;
        g_ndead[b] = NN - tot;
        int nrem = (int)((float)n_nodes[b] * 0.5f);
        out_nn[b] = (float)(n_nodes[b] - nrem);
    }
}

// ---------------- K_gather: 4 rows per block, bitmap decode, float4 channels ----------------
__global__ __launch_bounds__(256) void k_gather(const float* __restrict__ x) {
    int b = blockIdx.y;
    int nrows = g_nrows[b];
    if (blockIdx.x * 4 >= nrows) return;
    int tid = threadIdx.x;
    int sub = tid >> 6;        // row within block
    int ct  = tid & 63;        // float4 channel group
    int pos = blockIdx.x * 4 + sub;
    bool active = pos < nrows;

    __shared__ unsigned sbits[4][32];
    if (active && ct < 8) {
        int row = g_rows[b * NN + pos];
        ((uint4*)sbits[sub])[ct] =
            *((const uint4*)(g_bits + ((size_t)(b * NN) + row) * 32) + ct);
    }
    __syncthreads();
    if (!active) return;

    const float* xb = x + (size_t)b * NN * CC + ct * 4;
    float4 a[4];
#pragma unroll
    for (int u = 0; u < 4; u++) a[u] = make_float4(0.f, 0.f, 0.f, 0.f);
    for (int c = 0; c < 8; c++) {
#pragma unroll
        for (int u = 0; u < 4; u++) {
            unsigned w = sbits[sub][c * 4 + u];
            while (w) {
                int L = __ffs(w) - 1;
                w &= w - 1;
                float4 v = *(const float4*)(xb + (c * 128 + 4 * L + u) * CC);
                a[u].x += v.x; a[u].y += v.y; a[u].z += v.z; a[u].w += v.w;
            }
        }
    }
    float4 r;
    r.x = (a[0].x + a[1].x) + (a[2].x + a[3].x);
    r.y = (a[0].y + a[1].y) + (a[2].y + a[3].y);
    r.z = (a[0].z + a[1].z) + (a[2].z + a[3].z);
    r.w = (a[0].w + a[1].w) + (a[2].w + a[3].w);
    *(float4*)(g_gc + ((size_t)b * NN + pos) * CC + ct * 4) = r;
}

// ---------------- K_gemm: tf32 MMA, 3-term split, dead-row zeroing folded in ----------------
#define GM 128
#define GN 128
#define GK 16
#define AP 20    // A-tile k pitch (floats): conflict-free fragment loads
#define BPD 136  // B-tile n pitch

__global__ __launch_bounds__(256) void k_gemm(const float* __restrict__ W,
                                              const float* __restrict__ bvec,
                                              float* __restrict__ out_x) {
    __shared__ float Ah[GM][AP], Al[GM][AP];
    __shared__ float Bh[GK][BPD], Bl[GK][BPD];
    __shared__ float bs[GN];
    int b = blockIdx.z;
    int nrows = g_nrows[b];
    int row0 = blockIdx.x * GM;
    int col0 = blockIdx.y * GN;
    int tid = threadIdx.x;
    int lane = tid & 31, warp = tid >> 5;
    int wm = warp & 3, wn = warp >> 2;       // 4 M-warps x 2 N-warps
    int gid = lane >> 2, tig = lane & 3;

    if (tid < GN) bs[tid] = bvec[col0 + tid];

    float acc[2][8][4];
#pragma unroll
    for (int i = 0; i < 2; i++)
#pragma unroll
        for (int j = 0; j < 8; j++)
#pragma unroll
            for (int k = 0; k < 4; k++) acc[i][j][k] = 0.f;

    if (row0 < nrows) {
        int rows_in = nrows - row0; if (rows_in > GM) rows_in = GM;
        const float* A = g_gc + ((size_t)b * NN + row0) * CC;
        for (int kt = 0; kt < CC; kt += GK) {
#pragma unroll
            for (int u = 0; u < 2; u++) {
                int idx = tid + u * 256;
                int m = idx >> 2, k4 = idx & 3;
                float4 v = (m < rows_in)
                               ? *(const float4*)(A + (size_t)m * CC + kt + k4 * 4)
                               : make_float4(0.f, 0.f, 0.f, 0.f);
                float4 h4, l4;
                tf32split(v.x, h4.x, l4.x);
                tf32split(v.y, h4.y, l4.y);
                tf32split(v.z, h4.z, l4.z);
                tf32split(v.w, h4.w, l4.w);
                *(float4*)&Ah[m][k4 * 4] = h4;
                *(float4*)&Al[m][k4 * 4] = l4;
                int k = idx >> 5, c4 = idx & 31;
                float4 w = *(const float4*)(W + (size_t)(kt + k) * CC + col0 + c4 * 4);
                tf32split(w.x, h4.x, l4.x);
                tf32split(w.y, h4.y, l4.y);
                tf32split(w.z, h4.z, l4.z);
                tf32split(w.w, h4.w, l4.w);
                *(float4*)&Bh[k][c4 * 4] = h4;
                *(float4*)&Bl[k][c4 * 4] = l4;
            }
            __syncthreads();
#pragma unroll
            for (int k8 = 0; k8 < GK; k8 += 8) {
                unsigned ah[2][4], al[2][4], bh[8][2], bl[8][2];
#pragma unroll
                for (int mt = 0; mt < 2; mt++) {
                    int r = wm * 32 + mt * 16 + gid;
                    ah[mt][0] = __float_as_uint(Ah[r][k8 + tig]);
                    ah[mt][1] = __float_as_uint(Ah[r + 8][k8 + tig]);
                    ah[mt][2] = __float_as_uint(Ah[r][k8 + tig + 4]);
                    ah[mt][3] = __float_as_uint(Ah[r + 8][k8 + tig + 4]);
                    al[mt][0] = __float_as_uint(Al[r][k8 + tig]);
                    al[mt][1] = __float_as_uint(Al[r + 8][k8 + tig]);
                    al[mt][2] = __float_as_uint(Al[r][k8 + tig + 4]);
                    al[mt][3] = __float_as_uint(Al[r + 8][k8 + tig + 4]);
                }
#pragma unroll
                for (int nt = 0; nt < 8; nt++) {
                    int c = wn * 64 + nt * 8 + gid;
                    bh[nt][0] = __float_as_uint(Bh[k8 + tig][c]);
                    bh[nt][1] = __float_as_uint(Bh[k8 + tig + 4][c]);
                    bl[nt][0] = __float_as_uint(Bl[k8 + tig][c]);
                    bl[nt][1] = __float_as_uint(Bl[k8 + tig + 4][c]);
                }
#pragma unroll
                for (int mt = 0; mt < 2; mt++)
#pragma unroll
                    for (int nt = 0; nt < 8; nt++) {
                        MMA_TF32(acc[mt][nt], al[mt], bh[nt]);
                        MMA_TF32(acc[mt][nt], ah[mt], bl[nt]);
                        MMA_TF32(acc[mt][nt], ah[mt], bh[nt]);
                    }
            }
            __syncthreads();
        }
    }
    __syncthreads();   // bs visible for all paths (uniform)

#pragma unroll
    for (int mt = 0; mt < 2; mt++)
#pragma unroll
        for (int rh = 0; rh < 2; rh++) {
            int g = row0 + wm * 32 + mt * 16 + rh * 8 + gid;
            bool live = g < nrows;
            int node = live ? g_rows[b * NN + g] : g_dead[b * NN + g - nrows];
            float tval = live ? tanhf(g_y[b * NN + node]) : 0.f;
            float* orow = out_x + ((size_t)b * NN + node) * CC + col0 + wn * 64 + 2 * tig;
#pragma unroll
            for (int nt = 0; nt < 8; nt++) {
                float2 o;
                if (live) {
                    int c = wn * 64 + nt * 8 + 2 * tig;
                    o.x = (acc[mt][nt][rh * 2]     + bs[c])     * tval;
                    o.y = (acc[mt][nt][rh * 2 + 1] + bs[c + 1]) * tval;
                } else {
                    o.x = 0.f; o.y = 0.f;
                }
                *(float2*)(orow + nt * 8) = o;
            }
        }
}

// ---------------- K_adjout: dense bitmap expansion, 8 rows/block, full 1024 cols ----------------
__global__ __launch_bounds__(512) void k_adjout(float* __restrict__ out_adj) {
    int b = blockIdx.y;
    int tid = threadIdx.x;   // 512
    __shared__ float smf[NN];
    if (tid < 256) ((float4*)smf)[tid] = ((const float4*)(g_mf + b * NN))[tid];
    __syncthreads();
    int sub = tid >> 6, ct = tid & 63;
    int n = blockIdx.x * 8 + sub;
    float mfn = smf[n];
    const uint4* bwp = (const uint4*)(g_bits + ((size_t)(b * NN) + n) * 32);
    float4* orow = (float4*)(out_adj + ((size_t)b * NN + n) * NN);
#pragma unroll
    for (int u2 = 0; u2 < 4; u2++) {
        int cg = ct + u2 * 64;             // float4 column group 0..255
        uint4 bw = bwp[cg >> 5];           // chunk cg>>5 (0..7), words u0..u3
        int L = cg & 31;
        float4 mrow = ((const float4*)smf)[cg];   // mf for cols 4cg..4cg+3
        float4 o;
        o.x = ((bw.x >> L) & 1u) ? mfn * mrow.x : 0.f;
        o.y = ((bw.y >> L) & 1u) ? mfn * mrow.y : 0.f;
        o.z = ((bw.z >> L) & 1u) ? mfn * mrow.z : 0.f;
        o.w = ((bw.w >> L) & 1u) ? mfn * mrow.w : 0.f;
        orow[cg] = o;
    }
}

// ---------------- launch ----------------
extern "C" void kernel_launch(void* const* d_in, const int* in_sizes, int n_in,
                              void* d_out, int out_size) {
    const float* x    = (const float*)d_in[0];  // [B,N,C]
    const float* adj  = (const float*)d_in[1];  // [B,N,N]
    const int*   mask = (const int*)d_in[2];    // [B,N]
    const int*   nnod = (const int*)d_in[3];    // [B]
    const float* W    = (const float*)d_in[4];  // [C,C]
    const float* bv   = (const float*)d_in[5];  // [C]
    const float* pool = (const float*)d_in[6];  // [C,1]

    float* out = (float*)d_out;
    float* out_x    = out;                                   // B*N*C
    float* out_adj  = out + (size_t)BB * NN * CC;            // B*N*N
    float* out_mask = out_adj + (size_t)BB * NN * NN;        // B*N
    float* out_nn   = out_mask + (size_t)BB * NN;            // B

    // side stream + fork/join events (host-side resources only)
    cudaStream_t s2;
    cudaEvent_t eF, eJ;
    cudaStreamCreateWithFlags(&s2, cudaStreamNonBlocking);
    cudaEventCreateWithFlags(&eF, cudaEventDisableTiming);
    cudaEventCreateWithFlags(&eJ, cudaEventDisableTiming);

    k_prep<<<33, 256>>>(W, bv, pool);
    k_t<<<(BB * NN) / 8, 256>>>(x);
    k_adjscan<<<(BB * NN) / 8, 256>>>(adj);
    k_rank<<<dim3(8, BB), 1024>>>(mask, nnod, out_mask);

    // fork: adjout needs only g_mf (rank) + g_bits (adjscan)
    cudaEventRecord(eF, 0);
    cudaStreamWaitEvent(s2, eF, 0);
    k_adjout<<<dim3(NN / 8, BB), 512, 0, s2>>>(out_adj);
    cudaEventRecord(eJ, s2);

    k_compact<<<BB, 1024>>>(nnod, out_nn);
    k_gather<<<dim3(NN / 4, BB), 256>>>(x);
    k_gemm<<<dim3(NN / GM, CC / GN, BB), 256>>>(W, bv, out_x);

    // join
    cudaStreamWaitEvent(0, eJ, 0);
}